// round 2
// baseline (speedup 1.0000x reference)
#include <cuda_runtime.h>
#include <math.h>

#define BB 128
#define CC 128
#define TN 2000
#define FF 64
#define HH 128
#define SEQN 10
#define KTERMS 40

// ---------------- scratch (device globals; no runtime allocation) -------------
__device__ float g_mean[BB*CC];
__device__ float g_cov[BB*CC*CC];
__device__ float g_adj[BB*CC*CC];
__device__ float g_t1[BB*TN*FF];
__device__ float g_t2[BB*TN*FF];
__device__ float g_tcn[BB*TN*FF];
__device__ float g_nf[BB*CC*FF];
__device__ float g_geo[BB*CC*FF];
__device__ float g_decay[BB*HH];
__device__ float g_seqin[BB*SEQN*HH];
__device__ float g_spksum;

// ---------------- zero the spike accumulator ---------------------------------
__global__ void k_zero() {
    if (threadIdx.x == 0) g_spksum = 0.0f;
}

// ---------------- per (b,c) mean over T --------------------------------------
__global__ void k_mean(const float* __restrict__ X) {
    int warp = (blockIdx.x * blockDim.x + threadIdx.x) >> 5;
    int lane = threadIdx.x & 31;
    if (warp >= BB * CC) return;
    const float* row = X + (size_t)warp * TN;
    float s = 0.f;
    for (int t = lane; t < TN; t += 32) s += row[t];
    #pragma unroll
    for (int o = 16; o; o >>= 1) s += __shfl_xor_sync(0xffffffffu, s, o);
    if (lane == 0) g_mean[warp] = s * (1.0f / TN);
}

// ---------------- cov = (X X^T - T m m^T)/(T-1) + 1e-4 I ---------------------
__global__ void k_cov(const float* __restrict__ X) {
    __shared__ float As[32][68];
    __shared__ float Bs[32][68];
    int b  = blockIdx.z;
    int i0 = blockIdx.x * 64;
    int j0 = blockIdx.y * 64;
    int tid = threadIdx.x;
    int tx = tid & 15, ty = tid >> 4;
    const float* Xb = X + (size_t)b * CC * TN;

    float acc[4][4];
    #pragma unroll
    for (int a = 0; a < 4; a++)
        #pragma unroll
        for (int c = 0; c < 4; c++) acc[a][c] = 0.f;

    for (int k0 = 0; k0 < TN; k0 += 32) {
        for (int idx = tid; idx < 64 * 32; idx += 256) {
            int i = idx >> 5, kk = idx & 31;
            int k = k0 + kk;
            As[kk][i] = (k < TN) ? Xb[(size_t)(i0 + i) * TN + k] : 0.f;
            Bs[kk][i] = (k < TN) ? Xb[(size_t)(j0 + i) * TN + k] : 0.f;
        }
        __syncthreads();
        #pragma unroll 8
        for (int kk = 0; kk < 32; kk++) {
            float4 av = *reinterpret_cast<const float4*>(&As[kk][ty * 4]);
            float4 bv = *reinterpret_cast<const float4*>(&Bs[kk][tx * 4]);
            float aa[4] = {av.x, av.y, av.z, av.w};
            float bb[4] = {bv.x, bv.y, bv.z, bv.w};
            #pragma unroll
            for (int a = 0; a < 4; a++)
                #pragma unroll
                for (int c = 0; c < 4; c++) acc[a][c] += aa[a] * bb[c];
        }
        __syncthreads();
    }
    #pragma unroll
    for (int a = 0; a < 4; a++) {
        int i = i0 + ty * 4 + a;
        float mi = g_mean[b * CC + i];
        #pragma unroll
        for (int c = 0; c < 4; c++) {
            int j = j0 + tx * 4 + c;
            float mj = g_mean[b * CC + j];
            float v = (acc[a][c] - (float)TN * mi * mj) * (1.0f / (TN - 1));
            if (i == j) v += 1e-4f;
            g_cov[((size_t)b * CC + i) * CC + j] = v;
        }
    }
}

// ---------------- matrix log via Mercator series + row softmax ---------------
// log(A) = log(c) I - sum_{k=1..K} (I - A/c)^k / k,  c = 1.06 * trace/128
__global__ void k_logadj() {
    extern __shared__ float sm[];
    const int S = 128 * 132;
    float* Ms = sm;
    float* Ps = sm + S;
    float* Ls = sm + 2 * S;
    __shared__ float red[256];
    __shared__ float c_sh, logc_sh;

    int b = blockIdx.x, tid = threadIdx.x;
    const float* cov = g_cov + (size_t)b * CC * CC;

    float tv = (tid < 128) ? cov[tid * CC + tid] : 0.f;
    red[tid] = tv;
    __syncthreads();
    for (int o = 128; o; o >>= 1) {
        if (tid < o) red[tid] += red[tid + o];
        __syncthreads();
    }
    if (tid == 0) {
        float c = 1.06f * red[0] * (1.0f / 128.0f);
        c_sh = c;
        logc_sh = logf(c);
    }
    __syncthreads();
    float invc = 1.0f / c_sh;

    for (int idx = tid; idx < 128 * 128; idx += 256) {
        int i = idx >> 7, j = idx & 127;
        float m = ((i == j) ? 1.0f : 0.0f) - cov[idx] * invc;
        Ms[i * 132 + j] = m;
        Ps[i * 132 + j] = m;
        Ls[i * 132 + j] = -m;
    }
    __syncthreads();

    int r = tid >> 1, f0 = (tid & 1) * 64;
    for (int k = 2; k <= KTERMS; k++) {
        float acc[64];
        #pragma unroll
        for (int j = 0; j < 64; j++) acc[j] = 0.f;
        for (int kk = 0; kk < 128; kk++) {
            float p = Ps[r * 132 + kk];
            const float4* mrow = reinterpret_cast<const float4*>(&Ms[kk * 132 + f0]);
            #pragma unroll
            for (int q = 0; q < 16; q++) {
                float4 m4 = mrow[q];
                acc[4 * q + 0] += p * m4.x;
                acc[4 * q + 1] += p * m4.y;
                acc[4 * q + 2] += p * m4.z;
                acc[4 * q + 3] += p * m4.w;
            }
        }
        __syncthreads();
        float invk = 1.0f / (float)k;
        #pragma unroll
        for (int j = 0; j < 64; j++) {
            Ps[r * 132 + f0 + j] = acc[j];
            Ls[r * 132 + f0 + j] -= acc[j] * invk;
        }
        __syncthreads();
    }
    if (tid < 128) Ls[tid * 132 + tid] += logc_sh;
    __syncthreads();

    if (tid < 128) {
        float mx = -1e30f;
        for (int j = 0; j < 128; j++) mx = fmaxf(mx, Ls[tid * 132 + j]);
        float s = 0.f;
        for (int j = 0; j < 128; j++) {
            float e = expf(Ls[tid * 132 + j] - mx);
            Ms[tid * 132 + j] = e;
            s += e;
        }
        float inv = 1.0f / s;
        float* outp = g_adj + ((size_t)b * CC + tid) * CC;
        for (int j = 0; j < 128; j++) outp[j] = Ms[tid * 132 + j] * inv;
    }
}

// ---------------- conv1 (C=128 -> F=64, dil 1) + LN + relu + res1 ------------
__global__ void k_conv1(const float* __restrict__ X,
                        const float* __restrict__ w1, const float* __restrict__ b1,
                        const float* __restrict__ lns, const float* __restrict__ lnb,
                        const float* __restrict__ rw, const float* __restrict__ rb) {
    extern __shared__ float sm[];
    float* Xs = sm;                       // 128 x 130
    float* Ws = sm + 128 * 130;           // 3*128*64
    float* Rs = Ws + 3 * 128 * 64;        // 128*64
    int b = blockIdx.y;
    int t0 = blockIdx.x * 128;
    int tid = threadIdx.x;
    const float* Xb = X + (size_t)b * CC * TN;

    for (int idx = tid; idx < 128 * 130; idx += 256) {
        int c = idx / 130, u = idx % 130;
        int t = t0 - 1 + u;
        Xs[c * 130 + u] = (t >= 0 && t < TN) ? Xb[(size_t)c * TN + t] : 0.f;
    }
    for (int idx = tid; idx < 3 * 128 * 64; idx += 256) Ws[idx] = w1[idx];
    for (int idx = tid; idx < 128 * 64; idx += 256) Rs[idx] = rw[idx];
    __syncthreads();

    int tl = tid >> 1, f0 = (tid & 1) * 32;
    float acc[32], racc[32];
    #pragma unroll
    for (int j = 0; j < 32; j++) { acc[j] = b1[f0 + j]; racc[j] = rb[f0 + j]; }

    for (int c = 0; c < 128; c++) {
        float x0 = Xs[c * 130 + tl];
        float x1 = Xs[c * 130 + tl + 1];
        float x2 = Xs[c * 130 + tl + 2];
        const float4* w0 = reinterpret_cast<const float4*>(&Ws[(0 * 128 + c) * 64 + f0]);
        const float4* w1p = reinterpret_cast<const float4*>(&Ws[(1 * 128 + c) * 64 + f0]);
        const float4* w2p = reinterpret_cast<const float4*>(&Ws[(2 * 128 + c) * 64 + f0]);
        const float4* rp  = reinterpret_cast<const float4*>(&Rs[c * 64 + f0]);
        #pragma unroll
        for (int q = 0; q < 8; q++) {
            float4 a = w0[q], d = w1p[q], e = w2p[q], r4 = rp[q];
            acc[4*q+0] += x0 * a.x + x1 * d.x + x2 * e.x;
            acc[4*q+1] += x0 * a.y + x1 * d.y + x2 * e.y;
            acc[4*q+2] += x0 * a.z + x1 * d.z + x2 * e.z;
            acc[4*q+3] += x0 * a.w + x1 * d.w + x2 * e.w;
            racc[4*q+0] += x1 * r4.x;
            racc[4*q+1] += x1 * r4.y;
            racc[4*q+2] += x1 * r4.z;
            racc[4*q+3] += x1 * r4.w;
        }
    }
    float s = 0.f, ss = 0.f;
    #pragma unroll
    for (int j = 0; j < 32; j++) { s += acc[j]; ss += acc[j] * acc[j]; }
    s  += __shfl_xor_sync(0xffffffffu, s, 1);
    ss += __shfl_xor_sync(0xffffffffu, ss, 1);
    float m = s * (1.0f / 64.0f);
    float v = ss * (1.0f / 64.0f) - m * m;
    float rstd = rsqrtf(v + 1e-6f);

    int t = t0 + tl;
    if (t < TN) {
        float* o = g_t1 + ((size_t)b * TN + t) * 64 + f0;
        #pragma unroll
        for (int j = 0; j < 32; j++) {
            float h = fmaxf((acc[j] - m) * rstd * lns[f0 + j] + lnb[f0 + j], 0.f);
            acc[j] = h + racc[j];
        }
        #pragma unroll
        for (int q = 0; q < 8; q++) {
            float4 w4 = make_float4(acc[4*q], acc[4*q+1], acc[4*q+2], acc[4*q+3]);
            reinterpret_cast<float4*>(o)[q] = w4;
        }
    }
}

// ---------------- conv (F->F, dilation D) + LN + relu + identity res ---------
template <int D>
__global__ void k_convres(const float* __restrict__ in,
                          const float* __restrict__ w, const float* __restrict__ bias,
                          const float* __restrict__ lns, const float* __restrict__ lnb,
                          float* __restrict__ outp) {
    extern __shared__ float sm[];
    const int ROWS = 128 + 2 * D;
    float* Ts = sm;                 // ROWS x 65 (padded)
    float* Ws = sm + ROWS * 65;     // 3*64*64
    int b = blockIdx.y;
    int t0 = blockIdx.x * 128;
    int tid = threadIdx.x;
    const float* inb = in + (size_t)b * TN * 64;

    for (int idx = tid; idx < ROWS * 64; idx += 256) {
        int u = idx >> 6, f = idx & 63;
        int t = t0 - D + u;
        Ts[u * 65 + f] = (t >= 0 && t < TN) ? inb[(size_t)t * 64 + f] : 0.f;
    }
    for (int idx = tid; idx < 3 * 64 * 64; idx += 256) Ws[idx] = w[idx];
    __syncthreads();

    int tl = tid >> 1, f0 = (tid & 1) * 32;
    float acc[32];
    #pragma unroll
    for (int j = 0; j < 32; j++) acc[j] = bias[f0 + j];

    for (int c = 0; c < 64; c++) {
        float x0 = Ts[(tl + 0 * D) * 65 + c];
        float x1 = Ts[(tl + 1 * D) * 65 + c];
        float x2 = Ts[(tl + 2 * D) * 65 + c];
        const float4* w0 = reinterpret_cast<const float4*>(&Ws[(0 * 64 + c) * 64 + f0]);
        const float4* w1p = reinterpret_cast<const float4*>(&Ws[(1 * 64 + c) * 64 + f0]);
        const float4* w2p = reinterpret_cast<const float4*>(&Ws[(2 * 64 + c) * 64 + f0]);
        #pragma unroll
        for (int q = 0; q < 8; q++) {
            float4 a = w0[q], d = w1p[q], e = w2p[q];
            acc[4*q+0] += x0 * a.x + x1 * d.x + x2 * e.x;
            acc[4*q+1] += x0 * a.y + x1 * d.y + x2 * e.y;
            acc[4*q+2] += x0 * a.z + x1 * d.z + x2 * e.z;
            acc[4*q+3] += x0 * a.w + x1 * d.w + x2 * e.w;
        }
    }
    float s = 0.f, ss = 0.f;
    #pragma unroll
    for (int j = 0; j < 32; j++) { s += acc[j]; ss += acc[j] * acc[j]; }
    s  += __shfl_xor_sync(0xffffffffu, s, 1);
    ss += __shfl_xor_sync(0xffffffffu, ss, 1);
    float m = s * (1.0f / 64.0f);
    float v = ss * (1.0f / 64.0f) - m * m;
    float rstd = rsqrtf(v + 1e-6f);

    int t = t0 + tl;
    if (t < TN) {
        float* o = outp + ((size_t)b * TN + t) * 64 + f0;
        #pragma unroll
        for (int j = 0; j < 32; j++) {
            float h = fmaxf((acc[j] - m) * rstd * lns[f0 + j] + lnb[f0 + j], 0.f);
            acc[j] = h + Ts[(tl + D) * 65 + f0 + j];
        }
        #pragma unroll
        for (int q = 0; q < 8; q++) {
            float4 w4 = make_float4(acc[4*q], acc[4*q+1], acc[4*q+2], acc[4*q+3]);
            reinterpret_cast<float4*>(o)[q] = w4;
        }
    }
}

// ---------------- node_feats = X @ tcn_out  (B,C,T)@(B,T,F) ------------------
__global__ void k_nf(const float* __restrict__ X) {
    __shared__ float Xs[128][33];
    __shared__ float Ts[32][64];
    int b = blockIdx.x, tid = threadIdx.x;
    int c0 = (tid >> 4) * 8;
    int f0 = (tid & 15) * 4;
    float acc[8][4];
    #pragma unroll
    for (int r = 0; r < 8; r++)
        #pragma unroll
        for (int j = 0; j < 4; j++) acc[r][j] = 0.f;

    const float* Xb = X + (size_t)b * CC * TN;
    const float* Tb = g_tcn + (size_t)b * TN * 64;

    for (int k0 = 0; k0 < TN; k0 += 32) {
        for (int idx = tid; idx < 128 * 32; idx += 256) {
            int c = idx >> 5, kk = idx & 31;
            int k = k0 + kk;
            Xs[c][kk] = (k < TN) ? Xb[(size_t)c * TN + k] : 0.f;
        }
        for (int idx = tid; idx < 32 * 64; idx += 256) {
            int kk = idx >> 6, f = idx & 63;
            int k = k0 + kk;
            Ts[kk][f] = (k < TN) ? Tb[(size_t)k * 64 + f] : 0.f;
        }
        __syncthreads();
        #pragma unroll 4
        for (int kk = 0; kk < 32; kk++) {
            float4 t4 = *reinterpret_cast<const float4*>(&Ts[kk][f0]);
            float tb[4] = {t4.x, t4.y, t4.z, t4.w};
            #pragma unroll
            for (int r = 0; r < 8; r++) {
                float x = Xs[c0 + r][kk];
                #pragma unroll
                for (int j = 0; j < 4; j++) acc[r][j] += x * tb[j];
            }
        }
        __syncthreads();
    }
    #pragma unroll
    for (int r = 0; r < 8; r++) {
        float* o = g_nf + ((size_t)b * 128 + c0 + r) * 64 + f0;
        #pragma unroll
        for (int j = 0; j < 4; j++) o[j] = acc[r][j];
    }
}

// ---------------- geo = relu(LN(adj @ node_feats)) ---------------------------
__global__ void k_geo(const float* __restrict__ lns, const float* __restrict__ lnb) {
    __shared__ float nfs[128 * 64];
    int b = blockIdx.x, tid = threadIdx.x;   // 128 threads
    for (int idx = tid; idx < 128 * 64; idx += 128)
        nfs[idx] = g_nf[(size_t)b * 128 * 64 + idx];
    __syncthreads();

    const float* arow = g_adj + ((size_t)b * 128 + tid) * 128;
    float acc[64];
    #pragma unroll
    for (int j = 0; j < 64; j++) acc[j] = 0.f;
    for (int j = 0; j < 128; j++) {
        float a = arow[j];
        const float4* n4 = reinterpret_cast<const float4*>(&nfs[j * 64]);
        #pragma unroll
        for (int q = 0; q < 16; q++) {
            float4 v = n4[q];
            acc[4*q+0] += a * v.x;
            acc[4*q+1] += a * v.y;
            acc[4*q+2] += a * v.z;
            acc[4*q+3] += a * v.w;
        }
    }
    float s = 0.f, ss = 0.f;
    #pragma unroll
    for (int j = 0; j < 64; j++) { s += acc[j]; ss += acc[j] * acc[j]; }
    float m = s * (1.0f / 64.0f);
    float v = ss * (1.0f / 64.0f) - m * m;
    float rstd = rsqrtf(v + 1e-6f);
    float* o = g_geo + ((size_t)b * 128 + tid) * 64;
    #pragma unroll
    for (int j = 0; j < 64; j++)
        o[j] = fmaxf((acc[j] - m) * rstd * lns[j] + lnb[j], 0.f);
}

// ---------------- decay = sigmoid(gflat @ decay_w + b) -----------------------
__global__ void k_decay(const float* __restrict__ dw, const float* __restrict__ db) {
    __shared__ float gs[8192];
    int b = blockIdx.x, tid = threadIdx.x;  // 128 threads
    for (int idx = tid; idx < 8192; idx += 128)
        gs[idx] = g_geo[(size_t)b * 8192 + idx];
    __syncthreads();
    float acc = db[tid];
    #pragma unroll 4
    for (int k = 0; k < 8192; k++)
        acc += gs[k] * dw[(size_t)k * 128 + tid];
    g_decay[b * 128 + tid] = 1.0f / (1.0f + expf(-acc));
}

// ---------------- chunk-mean pool of tcn + seq_w GEMM ------------------------
__global__ void k_poolseq(const float* __restrict__ sw, const float* __restrict__ sb) {
    __shared__ float ps[64];
    int s = blockIdx.x, b = blockIdx.y, tid = threadIdx.x;  // 128 threads
    if (tid < 64) {
        const float* base = g_tcn + ((size_t)b * TN + s * 200) * 64 + tid;
        float a = 0.f;
        for (int t = 0; t < 200; t++) a += base[(size_t)t * 64];
        ps[tid] = a * (1.0f / 200.0f);
    }
    __syncthreads();
    float acc = sb[tid];
    #pragma unroll
    for (int f = 0; f < 64; f++) acc += ps[f] * sw[f * 128 + tid];
    g_seqin[((size_t)b * SEQN + s) * 128 + tid] = acc;
}

// ---------------- LIF scan + attention + heads -------------------------------
__global__ void k_lif(const float* __restrict__ aw, const float* __restrict__ ab,
                      const float* __restrict__ fw, const float* __restrict__ fb,
                      const float* __restrict__ ow, const float* __restrict__ ob,
                      float* __restrict__ dout) {
    __shared__ float red[128];
    __shared__ float attn[SEQN];
    __shared__ float featv[128];
    __shared__ float f2[64];
    int b = blockIdx.x, h = threadIdx.x;   // 128 threads

    float d = g_decay[b * 128 + h];
    float mem = 0.f, spsum = 0.f;
    float sp[SEQN];
    #pragma unroll
    for (int s = 0; s < SEQN; s++) {
        mem = mem * d + g_seqin[((size_t)b * SEQN + s) * 128 + h];
        float spike = (mem - 0.5f) > 0.f ? 1.0f : 0.0f;
        sp[s] = spike;
        spsum += spike;
        mem -= 0.5f * spike;
    }
    float awh = aw[h];
    for (int s = 0; s < SEQN; s++) {
        red[h] = sp[s] * awh;
        __syncthreads();
        for (int o = 64; o; o >>= 1) {
            if (h < o) red[h] += red[h + o];
            __syncthreads();
        }
        if (h == 0) attn[s] = red[0] + ab[0];
        __syncthreads();
    }
    red[h] = spsum;
    __syncthreads();
    for (int o = 64; o; o >>= 1) {
        if (h < o) red[h] += red[h + o];
        __syncthreads();
    }
    if (h == 0) atomicAdd(&g_spksum, red[0]);

    if (h == 0) {
        float mx = -1e30f;
        for (int s = 0; s < SEQN; s++) mx = fmaxf(mx, attn[s]);
        float ssum = 0.f;
        for (int s = 0; s < SEQN; s++) { attn[s] = expf(attn[s] - mx); ssum += attn[s]; }
        float inv = 1.0f / ssum;
        for (int s = 0; s < SEQN; s++) attn[s] *= inv;
    }
    __syncthreads();

    float fv = 0.f;
    #pragma unroll
    for (int s = 0; s < SEQN; s++) fv += sp[s] * attn[s];
    featv[h] = fv;
    __syncthreads();

    if (h < 64) {
        float acc = fb[h];
        for (int k = 0; k < 128; k++) acc += featv[k] * fw[k * 64 + h];
        f2[h] = fmaxf(acc, 0.f);
    }
    __syncthreads();
    if (h < 4) {
        float acc = ob[h];
        for (int j = 0; j < 64; j++) acc += f2[j] * ow[j * 4 + h];
        dout[b * 4 + h] = acc;
    }
}

__global__ void k_finmean(float* __restrict__ dout, int osz) {
    if (threadIdx.x == 0)
        dout[osz - 1] = g_spksum * (1.0f / ((float)BB * SEQN * HH));
}

// ---------------- launcher ----------------------------------------------------
extern "C" void kernel_launch(void* const* d_in, const int* in_sizes, int n_in,
                              void* d_out, int out_size) {
    const float* X    = (const float*)d_in[0];
    const float* c1w  = (const float*)d_in[1];
    const float* c1b  = (const float*)d_in[2];
    const float* l1s  = (const float*)d_in[3];
    const float* l1b  = (const float*)d_in[4];
    const float* r1w  = (const float*)d_in[5];
    const float* r1b  = (const float*)d_in[6];
    const float* c2w  = (const float*)d_in[7];
    const float* c2b  = (const float*)d_in[8];
    const float* l2s  = (const float*)d_in[9];
    const float* l2b  = (const float*)d_in[10];
    const float* c3w  = (const float*)d_in[11];
    const float* c3b  = (const float*)d_in[12];
    const float* l3s  = (const float*)d_in[13];
    const float* l3b  = (const float*)d_in[14];
    const float* lgs  = (const float*)d_in[15];
    const float* lgb  = (const float*)d_in[16];
    // d_in[17], d_in[18] = mix_w / mix_b : dead code in the reference
    const float* seqw = (const float*)d_in[19];
    const float* seqb = (const float*)d_in[20];
    const float* dw   = (const float*)d_in[21];
    const float* db   = (const float*)d_in[22];
    const float* aw   = (const float*)d_in[23];
    const float* ab   = (const float*)d_in[24];
    const float* fw   = (const float*)d_in[25];
    const float* fb   = (const float*)d_in[26];
    const float* ow   = (const float*)d_in[27];
    const float* ob   = (const float*)d_in[28];
    float* out = (float*)d_out;

    float *t1p, *t2p, *tcnp;
    cudaGetSymbolAddress((void**)&t1p, g_t1);
    cudaGetSymbolAddress((void**)&t2p, g_t2);
    cudaGetSymbolAddress((void**)&tcnp, g_tcn);

    size_t sm_log = (size_t)3 * 128 * 132 * sizeof(float);
    size_t sm_c1  = (size_t)(128 * 130 + 3 * 128 * 64 + 128 * 64) * sizeof(float);
    size_t sm_c2  = (size_t)((128 + 4) * 65 + 3 * 64 * 64) * sizeof(float);
    size_t sm_c3  = (size_t)((128 + 8) * 65 + 3 * 64 * 64) * sizeof(float);
    cudaFuncSetAttribute(k_logadj, cudaFuncAttributeMaxDynamicSharedMemorySize, (int)sm_log);
    cudaFuncSetAttribute(k_conv1, cudaFuncAttributeMaxDynamicSharedMemorySize, (int)sm_c1);
    cudaFuncSetAttribute(k_convres<2>, cudaFuncAttributeMaxDynamicSharedMemorySize, (int)sm_c2);
    cudaFuncSetAttribute(k_convres<4>, cudaFuncAttributeMaxDynamicSharedMemorySize, (int)sm_c3);

    k_zero<<<1, 32>>>();
    k_mean<<<(BB * CC * 32) / 256, 256>>>(X);
    {
        dim3 g(2, 2, BB);
        k_cov<<<g, 256>>>(X);
    }
    k_logadj<<<BB, 256, sm_log>>>();
    {
        dim3 g(16, BB);
        k_conv1<<<g, 256, sm_c1>>>(X, c1w, c1b, l1s, l1b, r1w, r1b);
        k_convres<2><<<g, 256, sm_c2>>>(t1p, c2w, c2b, l2s, l2b, t2p);
        k_convres<4><<<g, 256, sm_c3>>>(t2p, c3w, c3b, l3s, l3b, tcnp);
    }
    k_nf<<<BB, 256>>>(X);
    k_geo<<<BB, 128>>>(lgs, lgb);
    k_decay<<<BB, 128>>>(dw, db);
    {
        dim3 g(SEQN, BB);
        k_poolseq<<<g, 128>>>(seqw, seqb);
    }
    k_lif<<<BB, 128>>>(aw, ab, fw, fb, ow, ob, out);
    k_finmean<<<1, 32>>>(out, out_size);
}

// round 4
// speedup vs baseline: 1.3880x; 1.3880x over previous
#include <cuda_runtime.h>
#include <math.h>

#define BB 128
#define CC 128
#define TN 2000
#define FF 64
#define HH 128
#define SEQN 10
#define KTERMS 20

// ---------------- scratch (device globals; no runtime allocation) -------------
__device__ float g_mean[BB*CC];
__device__ float g_cov[BB*CC*CC];
__device__ float g_adj[BB*CC*CC];
__device__ float g_t1[BB*TN*FF];
__device__ float g_t2[BB*TN*FF];
__device__ float g_tcn[BB*TN*FF];
__device__ float g_nf[2*BB*CC*FF];     // two K-partials, summed in k_geo
__device__ float g_geo[BB*CC*FF];
__device__ float g_decay[BB*HH];
__device__ float g_seqin[BB*SEQN*HH];
__device__ float g_spksum;

__global__ void k_zero() {
    if (threadIdx.x == 0) g_spksum = 0.0f;
}

// ---------------- per (b,c) mean over T --------------------------------------
__global__ void k_mean(const float* __restrict__ X) {
    int warp = (blockIdx.x * blockDim.x + threadIdx.x) >> 5;
    int lane = threadIdx.x & 31;
    if (warp >= BB * CC) return;
    const float* row = X + (size_t)warp * TN;
    float s = 0.f;
    for (int t = lane; t < TN; t += 32) s += row[t];
    #pragma unroll
    for (int o = 16; o; o >>= 1) s += __shfl_xor_sync(0xffffffffu, s, o);
    if (lane == 0) g_mean[warp] = s * (1.0f / TN);
}

// ---------------- cov = (X X^T - T m m^T)/(T-1) + 1e-4 I  (symmetric) --------
// blockIdx.x in {0,1,2}: (i0,j0) = (0,0),(0,64),(64,64); mirror-write both halves
__global__ void k_cov(const float* __restrict__ X) {
    __shared__ float As[32][68];
    __shared__ float Bs[32][68];
    int b  = blockIdx.y;
    int blk = blockIdx.x;
    int i0 = (blk == 2) ? 64 : 0;
    int j0 = (blk == 0) ? 0 : 64;
    int tid = threadIdx.x;
    int tx = tid & 15, ty = tid >> 4;
    const float* Xb = X + (size_t)b * CC * TN;

    float acc[4][4];
    #pragma unroll
    for (int a = 0; a < 4; a++)
        #pragma unroll
        for (int c = 0; c < 4; c++) acc[a][c] = 0.f;

    for (int k0 = 0; k0 < TN; k0 += 32) {
        for (int idx = tid; idx < 64 * 32; idx += 256) {
            int i = idx >> 5, kk = idx & 31;
            int k = k0 + kk;
            As[kk][i] = (k < TN) ? Xb[(size_t)(i0 + i) * TN + k] : 0.f;
            Bs[kk][i] = (k < TN) ? Xb[(size_t)(j0 + i) * TN + k] : 0.f;
        }
        __syncthreads();
        #pragma unroll 8
        for (int kk = 0; kk < 32; kk++) {
            float4 av = *reinterpret_cast<const float4*>(&As[kk][ty * 4]);
            float4 bv = *reinterpret_cast<const float4*>(&Bs[kk][tx * 4]);
            float aa[4] = {av.x, av.y, av.z, av.w};
            float bb[4] = {bv.x, bv.y, bv.z, bv.w};
            #pragma unroll
            for (int a = 0; a < 4; a++)
                #pragma unroll
                for (int c = 0; c < 4; c++) acc[a][c] += aa[a] * bb[c];
        }
        __syncthreads();
    }
    float* covb = g_cov + (size_t)b * CC * CC;
    #pragma unroll
    for (int a = 0; a < 4; a++) {
        int i = i0 + ty * 4 + a;
        float mi = g_mean[b * CC + i];
        #pragma unroll
        for (int c = 0; c < 4; c++) {
            int j = j0 + tx * 4 + c;
            float mj = g_mean[b * CC + j];
            float v = (acc[a][c] - (float)TN * mi * mj) * (1.0f / (TN - 1));
            if (i == j) v += 1e-4f;
            covb[(size_t)i * CC + j] = v;
            covb[(size_t)j * CC + i] = v;
        }
    }
}

// ---------------- matrix log (Mercator, symmetric trick) + row softmax -------
// log(A) = log(c) I - sum_{k=1..K} (I - A/c)^k / k,  c = 1.06 * trace/128
// M = I - A/c is symmetric => all powers symmetric => P[r][kk] = P[kk][r],
// so both GEMM operands are contiguous row reads at uniform kk.
__global__ void __launch_bounds__(256, 1) k_logadj() {
    extern __shared__ float sm[];
    float* Ms = sm;
    float* Pa = sm + 16384;
    float* Pb = sm + 32768;
    __shared__ float red[128];
    __shared__ float csh[2];

    int b = blockIdx.x, tid = threadIdx.x;
    const float* cov = g_cov + (size_t)b * CC * CC;

    if (tid < 128) red[tid] = cov[tid * 129];
    __syncthreads();
    for (int o = 64; o; o >>= 1) {
        if (tid < o) red[tid] += red[tid + o];
        __syncthreads();
    }
    if (tid == 0) {
        float c = 1.06f * red[0] * (1.0f / 128.0f);
        csh[0] = 1.0f / c;
        csh[1] = logf(c);
    }
    __syncthreads();
    float invc = csh[0];

    for (int idx = tid; idx < 16384; idx += 256) {
        int i = idx >> 7, j = idx & 127;
        float m = ((i == j) ? 1.0f : 0.0f) - cov[idx] * invc;
        Ms[idx] = m;
        Pa[idx] = m;
    }
    __syncthreads();

    int ty = tid >> 4, tx = tid & 15;
    int r0 = ty * 8, c0 = tx * 8;

    float La[8][8];
    #pragma unroll
    for (int i = 0; i < 8; i++)
        #pragma unroll
        for (int j = 0; j < 8; j++) La[i][j] = -Ms[(r0 + i) * 128 + c0 + j];

    float* Po = Pa;
    float* Pn = Pb;
    for (int k = 2; k <= KTERMS; k++) {
        float acc[8][8];
        #pragma unroll
        for (int i = 0; i < 8; i++)
            #pragma unroll
            for (int j = 0; j < 8; j++) acc[i][j] = 0.f;

        #pragma unroll 4
        for (int kk = 0; kk < 128; kk++) {
            float4 p0 = *reinterpret_cast<const float4*>(&Po[kk * 128 + r0]);
            float4 p1 = *reinterpret_cast<const float4*>(&Po[kk * 128 + r0 + 4]);
            float4 m0 = *reinterpret_cast<const float4*>(&Ms[kk * 128 + c0]);
            float4 m1 = *reinterpret_cast<const float4*>(&Ms[kk * 128 + c0 + 4]);
            float pv[8] = {p0.x, p0.y, p0.z, p0.w, p1.x, p1.y, p1.z, p1.w};
            float mv[8] = {m0.x, m0.y, m0.z, m0.w, m1.x, m1.y, m1.z, m1.w};
            #pragma unroll
            for (int i = 0; i < 8; i++)
                #pragma unroll
                for (int j = 0; j < 8; j++) acc[i][j] += pv[i] * mv[j];
        }
        float invk = 1.0f / (float)k;
        #pragma unroll
        for (int i = 0; i < 8; i++) {
            *reinterpret_cast<float4*>(&Pn[(r0 + i) * 128 + c0]) =
                make_float4(acc[i][0], acc[i][1], acc[i][2], acc[i][3]);
            *reinterpret_cast<float4*>(&Pn[(r0 + i) * 128 + c0 + 4]) =
                make_float4(acc[i][4], acc[i][5], acc[i][6], acc[i][7]);
            #pragma unroll
            for (int j = 0; j < 8; j++) La[i][j] -= acc[i][j] * invk;
        }
        __syncthreads();
        float* tmp = Po; Po = Pn; Pn = tmp;
    }

    float logc = csh[1];
    #pragma unroll
    for (int i = 0; i < 8; i++) {
        int dj = (r0 + i) - c0;
        if (dj >= 0 && dj < 8) La[i][dj] += logc;
    }

    // row softmax: each row spread over 16 tx lanes (contiguous 16-lane groups)
    #pragma unroll
    for (int i = 0; i < 8; i++) {
        float mx = -1e30f;
        #pragma unroll
        for (int j = 0; j < 8; j++) mx = fmaxf(mx, La[i][j]);
        #pragma unroll
        for (int o = 1; o < 16; o <<= 1) mx = fmaxf(mx, __shfl_xor_sync(0xffffffffu, mx, o));
        float e[8], s = 0.f;
        #pragma unroll
        for (int j = 0; j < 8; j++) { e[j] = expf(La[i][j] - mx); s += e[j]; }
        #pragma unroll
        for (int o = 1; o < 16; o <<= 1) s += __shfl_xor_sync(0xffffffffu, s, o);
        float inv = 1.0f / s;
        float* outp = g_adj + ((size_t)b * 128 + r0 + i) * 128 + c0;
        *reinterpret_cast<float4*>(outp) =
            make_float4(e[0] * inv, e[1] * inv, e[2] * inv, e[3] * inv);
        *reinterpret_cast<float4*>(outp + 4) =
            make_float4(e[4] * inv, e[5] * inv, e[6] * inv, e[7] * inv);
    }
}

// ---------------- conv1 (C=128 -> F=64, dil 1) + LN + relu + res1 ------------
// thread tile: 4 t x 8 f  (tg=tid>>3 over 32 t-groups, fg=tid&7 over 8 f-groups)
__global__ void __launch_bounds__(256, 1)
k_conv1(const float* __restrict__ X,
        const float* __restrict__ w1, const float* __restrict__ b1,
        const float* __restrict__ lns, const float* __restrict__ lnb,
        const float* __restrict__ rw, const float* __restrict__ rb) {
    extern __shared__ float sm[];
    float* Xs = sm;                       // 128 x 132 (130 used)
    float* Ws = sm + 128 * 132;           // 3*128*64
    float* Rs = Ws + 3 * 128 * 64;        // 128*64
    int b = blockIdx.y;
    int t0 = blockIdx.x * 128;
    int tid = threadIdx.x;
    const float* Xb = X + (size_t)b * CC * TN;

    for (int idx = tid; idx < 128 * 130; idx += 256) {
        int c = idx / 130, u = idx % 130;
        int t = t0 - 1 + u;
        Xs[c * 132 + u] = (t >= 0 && t < TN) ? Xb[(size_t)c * TN + t] : 0.f;
    }
    for (int idx = tid; idx < 3 * 128 * 64; idx += 256) Ws[idx] = w1[idx];
    for (int idx = tid; idx < 128 * 64; idx += 256) Rs[idx] = rw[idx];
    __syncthreads();

    int tg = tid >> 3, fg = tid & 7;
    int f0 = fg * 8;
    int u0 = tg * 4;

    float ls[8], lb[8];
    float acc[4][8], racc[4][8];
    #pragma unroll
    for (int j = 0; j < 8; j++) {
        ls[j] = lns[f0 + j];
        lb[j] = lnb[f0 + j];
        float bj = b1[f0 + j], rj = rb[f0 + j];
        #pragma unroll
        for (int i = 0; i < 4; i++) { acc[i][j] = bj; racc[i][j] = rj; }
    }

    for (int c = 0; c < 128; c++) {
        float x[6];
        #pragma unroll
        for (int s = 0; s < 6; s++) x[s] = Xs[c * 132 + u0 + s];
        float4 a0 = *reinterpret_cast<const float4*>(&Ws[c * 64 + f0]);
        float4 a1 = *reinterpret_cast<const float4*>(&Ws[c * 64 + f0 + 4]);
        float4 d0 = *reinterpret_cast<const float4*>(&Ws[(128 + c) * 64 + f0]);
        float4 d1 = *reinterpret_cast<const float4*>(&Ws[(128 + c) * 64 + f0 + 4]);
        float4 e0 = *reinterpret_cast<const float4*>(&Ws[(256 + c) * 64 + f0]);
        float4 e1 = *reinterpret_cast<const float4*>(&Ws[(256 + c) * 64 + f0 + 4]);
        float4 r0v = *reinterpret_cast<const float4*>(&Rs[c * 64 + f0]);
        float4 r1v = *reinterpret_cast<const float4*>(&Rs[c * 64 + f0 + 4]);
        float w0[8] = {a0.x, a0.y, a0.z, a0.w, a1.x, a1.y, a1.z, a1.w};
        float w1v[8] = {d0.x, d0.y, d0.z, d0.w, d1.x, d1.y, d1.z, d1.w};
        float w2[8] = {e0.x, e0.y, e0.z, e0.w, e1.x, e1.y, e1.z, e1.w};
        float rr[8] = {r0v.x, r0v.y, r0v.z, r0v.w, r1v.x, r1v.y, r1v.z, r1v.w};
        #pragma unroll
        for (int i = 0; i < 4; i++)
            #pragma unroll
            for (int j = 0; j < 8; j++) {
                acc[i][j] += x[i] * w0[j] + x[i + 1] * w1v[j] + x[i + 2] * w2[j];
                racc[i][j] += x[i + 1] * rr[j];
            }
    }

    #pragma unroll
    for (int i = 0; i < 4; i++) {
        float s = 0.f, ss = 0.f;
        #pragma unroll
        for (int j = 0; j < 8; j++) { s += acc[i][j]; ss += acc[i][j] * acc[i][j]; }
        #pragma unroll
        for (int o = 1; o < 8; o <<= 1) {
            s  += __shfl_xor_sync(0xffffffffu, s, o);
            ss += __shfl_xor_sync(0xffffffffu, ss, o);
        }
        float m = s * (1.0f / 64.0f);
        float v = ss * (1.0f / 64.0f) - m * m;
        float rstd = rsqrtf(v + 1e-6f);
        int t = t0 + tg * 4 + i;
        if (t < TN) {
            float o8[8];
            #pragma unroll
            for (int j = 0; j < 8; j++) {
                float h = fmaxf((acc[i][j] - m) * rstd * ls[j] + lb[j], 0.f);
                o8[j] = h + racc[i][j];
            }
            float* op = g_t1 + ((size_t)b * TN + t) * 64 + f0;
            *reinterpret_cast<float4*>(op) = make_float4(o8[0], o8[1], o8[2], o8[3]);
            *reinterpret_cast<float4*>(op + 4) = make_float4(o8[4], o8[5], o8[6], o8[7]);
        }
    }
}

// ---------------- conv (F->F, dilation D) + LN + relu + identity res ---------
template <int D>
__global__ void __launch_bounds__(256, 2)
k_convres(const float* __restrict__ in,
          const float* __restrict__ w, const float* __restrict__ bias,
          const float* __restrict__ lns, const float* __restrict__ lnb,
          float* __restrict__ outp) {
    extern __shared__ float sm[];
    const int ROWS = 128 + 2 * D;
    float* Ts = sm;                 // ROWS x 65
    float* Ws = sm + ROWS * 65;     // 3*64*64
    int b = blockIdx.y;
    int t0 = blockIdx.x * 128;
    int tid = threadIdx.x;
    const float* inb = in + (size_t)b * TN * 64;

    for (int idx = tid; idx < ROWS * 64; idx += 256) {
        int u = idx >> 6, f = idx & 63;
        int t = t0 - D + u;
        Ts[u * 65 + f] = (t >= 0 && t < TN) ? inb[(size_t)t * 64 + f] : 0.f;
    }
    for (int idx = tid; idx < 3 * 64 * 64; idx += 256) Ws[idx] = w[idx];
    __syncthreads();

    int tg = tid >> 3, fg = tid & 7;
    int f0 = fg * 8;
    int u0 = tg * 4;

    float ls[8], lb[8];
    float acc[4][8];
    #pragma unroll
    for (int j = 0; j < 8; j++) {
        ls[j] = lns[f0 + j];
        lb[j] = lnb[f0 + j];
        float bj = bias[f0 + j];
        #pragma unroll
        for (int i = 0; i < 4; i++) acc[i][j] = bj;
    }

    for (int c = 0; c < 64; c++) {
        float xs[2 * D + 4];
        #pragma unroll
        for (int s = 0; s < 2 * D + 4; s++) xs[s] = Ts[(u0 + s) * 65 + c];
        #pragma unroll
        for (int tap = 0; tap < 3; tap++) {
            float4 w0 = *reinterpret_cast<const float4*>(&Ws[tap * 4096 + c * 64 + f0]);
            float4 w1 = *reinterpret_cast<const float4*>(&Ws[tap * 4096 + c * 64 + f0 + 4]);
            float wv[8] = {w0.x, w0.y, w0.z, w0.w, w1.x, w1.y, w1.z, w1.w};
            #pragma unroll
            for (int i = 0; i < 4; i++) {
                float x = xs[i + tap * D];
                #pragma unroll
                for (int j = 0; j < 8; j++) acc[i][j] += x * wv[j];
            }
        }
    }

    #pragma unroll
    for (int i = 0; i < 4; i++) {
        float s = 0.f, ss = 0.f;
        #pragma unroll
        for (int j = 0; j < 8; j++) { s += acc[i][j]; ss += acc[i][j] * acc[i][j]; }
        #pragma unroll
        for (int o = 1; o < 8; o <<= 1) {
            s  += __shfl_xor_sync(0xffffffffu, s, o);
            ss += __shfl_xor_sync(0xffffffffu, ss, o);
        }
        float m = s * (1.0f / 64.0f);
        float v = ss * (1.0f / 64.0f) - m * m;
        float rstd = rsqrtf(v + 1e-6f);
        int t = t0 + tg * 4 + i;
        if (t < TN) {
            float o8[8];
            #pragma unroll
            for (int j = 0; j < 8; j++) {
                float h = fmaxf((acc[i][j] - m) * rstd * ls[j] + lb[j], 0.f);
                o8[j] = h + Ts[(u0 + i + D) * 65 + f0 + j];
            }
            float* op = outp + ((size_t)b * TN + t) * 64 + f0;
            *reinterpret_cast<float4*>(op) = make_float4(o8[0], o8[1], o8[2], o8[3]);
            *reinterpret_cast<float4*>(op + 4) = make_float4(o8[4], o8[5], o8[6], o8[7]);
        }
    }
}

// ---------------- node_feats = X @ tcn_out, K split over 2 CTAs --------------
__global__ void k_nf(const float* __restrict__ X) {
    __shared__ float Xs[128][33];
    __shared__ float Ts[32][64];
    int half = blockIdx.x;
    int b = blockIdx.y;
    int tid = threadIdx.x;
    int c0 = (tid >> 4) * 8;
    int f0 = (tid & 15) * 4;
    float acc[8][4];
    #pragma unroll
    for (int r = 0; r < 8; r++)
        #pragma unroll
        for (int j = 0; j < 4; j++) acc[r][j] = 0.f;

    const float* Xb = X + (size_t)b * CC * TN;
    const float* Tb = g_tcn + (size_t)b * TN * 64;
    int kbeg = half * 1000, kend = kbeg + 1000;

    for (int k0 = kbeg; k0 < kend; k0 += 32) {
        for (int idx = tid; idx < 128 * 32; idx += 256) {
            int c = idx >> 5, kk = idx & 31;
            int k = k0 + kk;
            Xs[c][kk] = (k < kend) ? Xb[(size_t)c * TN + k] : 0.f;
        }
        for (int idx = tid; idx < 32 * 64; idx += 256) {
            int kk = idx >> 6, f = idx & 63;
            int k = k0 + kk;
            Ts[kk][f] = (k < kend) ? Tb[(size_t)k * 64 + f] : 0.f;
        }
        __syncthreads();
        #pragma unroll 4
        for (int kk = 0; kk < 32; kk++) {
            float4 t4 = *reinterpret_cast<const float4*>(&Ts[kk][f0]);
            float tb[4] = {t4.x, t4.y, t4.z, t4.w};
            #pragma unroll
            for (int r = 0; r < 8; r++) {
                float x = Xs[c0 + r][kk];
                #pragma unroll
                for (int j = 0; j < 4; j++) acc[r][j] += x * tb[j];
            }
        }
        __syncthreads();
    }
    #pragma unroll
    for (int r = 0; r < 8; r++) {
        float* o = g_nf + (size_t)half * BB * CC * FF + ((size_t)b * 128 + c0 + r) * 64 + f0;
        #pragma unroll
        for (int j = 0; j < 4; j++) o[j] = acc[r][j];
    }
}

// ---------------- geo = relu(LN(adj @ node_feats)) ---------------------------
__global__ void k_geo(const float* __restrict__ lns, const float* __restrict__ lnb) {
    __shared__ float nfs[128 * 64];
    int b = blockIdx.x, tid = threadIdx.x;   // 128 threads
    for (int idx = tid; idx < 128 * 64; idx += 128)
        nfs[idx] = g_nf[(size_t)b * 8192 + idx] + g_nf[(size_t)BB * 8192 + (size_t)b * 8192 + idx];
    __syncthreads();

    const float* arow = g_adj + ((size_t)b * 128 + tid) * 128;
    float acc[64];
    #pragma unroll
    for (int j = 0; j < 64; j++) acc[j] = 0.f;
    for (int j = 0; j < 128; j++) {
        float a = arow[j];
        const float4* n4 = reinterpret_cast<const float4*>(&nfs[j * 64]);
        #pragma unroll
        for (int q = 0; q < 16; q++) {
            float4 v = n4[q];
            acc[4*q+0] += a * v.x;
            acc[4*q+1] += a * v.y;
            acc[4*q+2] += a * v.z;
            acc[4*q+3] += a * v.w;
        }
    }
    float s = 0.f, ss = 0.f;
    #pragma unroll
    for (int j = 0; j < 64; j++) { s += acc[j]; ss += acc[j] * acc[j]; }
    float m = s * (1.0f / 64.0f);
    float v = ss * (1.0f / 64.0f) - m * m;
    float rstd = rsqrtf(v + 1e-6f);
    float* o = g_geo + ((size_t)b * 128 + tid) * 64;
    #pragma unroll
    for (int j = 0; j < 64; j++)
        o[j] = fmaxf((acc[j] - m) * rstd * lns[j] + lnb[j], 0.f);
}

// ---------------- decay = sigmoid(gflat @ decay_w + b) -----------------------
__global__ void k_decay(const float* __restrict__ dw, const float* __restrict__ db) {
    __shared__ float gs[8192];
    int b = blockIdx.x, tid = threadIdx.x;  // 128 threads
    for (int idx = tid; idx < 8192; idx += 128)
        gs[idx] = g_geo[(size_t)b * 8192 + idx];
    __syncthreads();
    float a0 = 0.f, a1 = 0.f, a2 = 0.f, a3 = 0.f;
    for (int k = 0; k < 8192; k += 4) {
        a0 += gs[k + 0] * dw[(size_t)(k + 0) * 128 + tid];
        a1 += gs[k + 1] * dw[(size_t)(k + 1) * 128 + tid];
        a2 += gs[k + 2] * dw[(size_t)(k + 2) * 128 + tid];
        a3 += gs[k + 3] * dw[(size_t)(k + 3) * 128 + tid];
    }
    float acc = db[tid] + ((a0 + a1) + (a2 + a3));
    g_decay[b * 128 + tid] = 1.0f / (1.0f + expf(-acc));
}

// ---------------- chunk-mean pool of tcn + seq_w GEMM ------------------------
__global__ void k_poolseq(const float* __restrict__ sw, const float* __restrict__ sb) {
    __shared__ float ps[64];
    int s = blockIdx.x, b = blockIdx.y, tid = threadIdx.x;  // 128 threads
    if (tid < 64) {
        const float* base = g_tcn + ((size_t)b * TN + s * 200) * 64 + tid;
        float a = 0.f;
        for (int t = 0; t < 200; t++) a += base[(size_t)t * 64];
        ps[tid] = a * (1.0f / 200.0f);
    }
    __syncthreads();
    float acc = sb[tid];
    #pragma unroll
    for (int f = 0; f < 64; f++) acc += ps[f] * sw[f * 128 + tid];
    g_seqin[((size_t)b * SEQN + s) * 128 + tid] = acc;
}

// ---------------- LIF scan + attention + heads -------------------------------
__global__ void k_lif(const float* __restrict__ aw, const float* __restrict__ ab,
                      const float* __restrict__ fw, const float* __restrict__ fb,
                      const float* __restrict__ ow, const float* __restrict__ ob,
                      float* __restrict__ dout) {
    __shared__ float red[128];
    __shared__ float attn[SEQN];
    __shared__ float featv[128];
    __shared__ float f2[64];
    int b = blockIdx.x, h = threadIdx.x;   // 128 threads

    float d = g_decay[b * 128 + h];
    float mem = 0.f, spsum = 0.f;
    float sp[SEQN];
    #pragma unroll
    for (int s = 0; s < SEQN; s++) {
        mem = mem * d + g_seqin[((size_t)b * SEQN + s) * 128 + h];
        float spike = (mem - 0.5f) > 0.f ? 1.0f : 0.0f;
        sp[s] = spike;
        spsum += spike;
        mem -= 0.5f * spike;
    }
    float awh = aw[h];
    for (int s = 0; s < SEQN; s++) {
        red[h] = sp[s] * awh;
        __syncthreads();
        for (int o = 64; o; o >>= 1) {
            if (h < o) red[h] += red[h + o];
            __syncthreads();
        }
        if (h == 0) attn[s] = red[0] + ab[0];
        __syncthreads();
    }
    red[h] = spsum;
    __syncthreads();
    for (int o = 64; o; o >>= 1) {
        if (h < o) red[h] += red[h + o];
        __syncthreads();
    }
    if (h == 0) atomicAdd(&g_spksum, red[0]);

    if (h == 0) {
        float mx = -1e30f;
        for (int s = 0; s < SEQN; s++) mx = fmaxf(mx, attn[s]);
        float ssum = 0.f;
        for (int s = 0; s < SEQN; s++) { attn[s] = expf(attn[s] - mx); ssum += attn[s]; }
        float inv = 1.0f / ssum;
        for (int s = 0; s < SEQN; s++) attn[s] *= inv;
    }
    __syncthreads();

    float fv = 0.f;
    #pragma unroll
    for (int s = 0; s < SEQN; s++) fv += sp[s] * attn[s];
    featv[h] = fv;
    __syncthreads();

    if (h < 64) {
        float acc = fb[h];
        for (int k = 0; k < 128; k++) acc += featv[k] * fw[k * 64 + h];
        f2[h] = fmaxf(acc, 0.f);
    }
    __syncthreads();
    if (h < 4) {
        float acc = ob[h];
        for (int j = 0; j < 64; j++) acc += f2[j] * ow[j * 4 + h];
        dout[b * 4 + h] = acc;
    }
}

__global__ void k_finmean(float* __restrict__ dout, int osz) {
    if (threadIdx.x == 0)
        dout[osz - 1] = g_spksum * (1.0f / ((float)BB * SEQN * HH));
}

// ---------------- launcher ----------------------------------------------------
extern "C" void kernel_launch(void* const* d_in, const int* in_sizes, int n_in,
                              void* d_out, int out_size) {
    const float* X    = (const float*)d_in[0];
    const float* c1w  = (const float*)d_in[1];
    const float* c1b  = (const float*)d_in[2];
    const float* l1s  = (const float*)d_in[3];
    const float* l1b  = (const float*)d_in[4];
    const float* r1w  = (const float*)d_in[5];
    const float* r1b  = (const float*)d_in[6];
    const float* c2w  = (const float*)d_in[7];
    const float* c2b  = (const float*)d_in[8];
    const float* l2s  = (const float*)d_in[9];
    const float* l2b  = (const float*)d_in[10];
    const float* c3w  = (const float*)d_in[11];
    const float* c3b  = (const float*)d_in[12];
    const float* l3s  = (const float*)d_in[13];
    const float* l3b  = (const float*)d_in[14];
    const float* lgs  = (const float*)d_in[15];
    const float* lgb  = (const float*)d_in[16];
    // d_in[17], d_in[18] = mix_w / mix_b : dead code in the reference
    const float* seqw = (const float*)d_in[19];
    const float* seqb = (const float*)d_in[20];
    const float* dw   = (const float*)d_in[21];
    const float* db   = (const float*)d_in[22];
    const float* aw   = (const float*)d_in[23];
    const float* ab   = (const float*)d_in[24];
    const float* fw   = (const float*)d_in[25];
    const float* fb   = (const float*)d_in[26];
    const float* ow   = (const float*)d_in[27];
    const float* ob   = (const float*)d_in[28];
    float* out = (float*)d_out;

    float *t1p, *t2p, *tcnp;
    cudaGetSymbolAddress((void**)&t1p, g_t1);
    cudaGetSymbolAddress((void**)&t2p, g_t2);
    cudaGetSymbolAddress((void**)&tcnp, g_tcn);

    size_t sm_log = (size_t)3 * 128 * 128 * sizeof(float);                     // 192 KB
    size_t sm_c1  = (size_t)(128 * 132 + 3 * 128 * 64 + 128 * 64) * sizeof(float); // ~194 KB
    size_t sm_c2  = (size_t)(132 * 65 + 3 * 64 * 64) * sizeof(float);
    size_t sm_c3  = (size_t)(136 * 65 + 3 * 64 * 64) * sizeof(float);
    cudaFuncSetAttribute(k_logadj, cudaFuncAttributeMaxDynamicSharedMemorySize, (int)sm_log);
    cudaFuncSetAttribute(k_conv1, cudaFuncAttributeMaxDynamicSharedMemorySize, (int)sm_c1);
    cudaFuncSetAttribute(k_convres<2>, cudaFuncAttributeMaxDynamicSharedMemorySize, (int)sm_c2);
    cudaFuncSetAttribute(k_convres<4>, cudaFuncAttributeMaxDynamicSharedMemorySize, (int)sm_c3);

    k_zero<<<1, 32>>>();
    k_mean<<<(BB * CC * 32) / 256, 256>>>(X);
    {
        dim3 g(3, BB);
        k_cov<<<g, 256>>>(X);
    }
    k_logadj<<<BB, 256, sm_log>>>();
    {
        dim3 g(16, BB);
        k_conv1<<<g, 256, sm_c1>>>(X, c1w, c1b, l1s, l1b, r1w, r1b);
        k_convres<2><<<g, 256, sm_c2>>>(t1p, c2w, c2b, l2s, l2b, t2p);
        k_convres<4><<<g, 256, sm_c3>>>(t2p, c3w, c3b, l3s, l3b, tcnp);
    }
    {
        dim3 g(2, BB);
        k_nf<<<g, 256>>>(X);
    }
    k_geo<<<BB, 128>>>(lgs, lgb);
    k_decay<<<BB, 128>>>(dw, db);
    {
        dim3 g(SEQN, BB);
        k_poolseq<<<g, 128>>>(seqw, seqb);
    }
    k_lif<<<BB, 128>>>(aw, ab, fw, fb, ow, ob, out);
    k_finmean<<<1, 32>>>(out, out_size);
}

// round 5
// speedup vs baseline: 1.5612x; 1.1248x over previous
#include <cuda_runtime.h>
#include <math.h>

#define BB 128
#define CC 128
#define TN 2000
#define FF 64
#define HH 128
#define SEQN 10
#define KTERMS 20

typedef unsigned long long ull;

// ---- packed f32x2 helpers (sm_103a) -----------------------------------------
__device__ __forceinline__ ull d2(float x) {
    ull r; asm("mov.b64 %0, {%1, %1};" : "=l"(r) : "f"(x)); return r;
}
__device__ __forceinline__ ull pk2(float a, float b) {
    ull r; asm("mov.b64 %0, {%1, %2};" : "=l"(r) : "f"(a), "f"(b)); return r;
}
__device__ __forceinline__ void up2(ull v, float& a, float& b) {
    asm("mov.b64 {%0, %1}, %2;" : "=f"(a), "=f"(b) : "l"(v));
}
__device__ __forceinline__ void fma2(ull& d, ull a, ull b) {
    asm("fma.rn.f32x2 %0, %1, %2, %0;" : "+l"(d) : "l"(a), "l"(b));
}
__device__ __forceinline__ ull mul2(ull a, ull b) {
    ull r; asm("mul.rn.f32x2 %0, %1, %2;" : "=l"(r) : "l"(a), "l"(b)); return r;
}

// ---------------- scratch (device globals; no runtime allocation) -------------
__device__ float g_mean[BB*CC];
__device__ float g_cov[BB*CC*CC];
__device__ float g_adj[BB*CC*CC];
__device__ float g_t1[BB*TN*FF];
__device__ float g_t2[BB*TN*FF];
__device__ float g_tcn[BB*TN*FF];
__device__ float g_nf[2*BB*CC*FF];     // two K-partials, summed in k_geo
__device__ float g_geo[BB*CC*FF];
__device__ float g_dpart[4*BB*HH];     // decay GEMV partials
__device__ float g_seqin[BB*SEQN*HH];
__device__ float g_spksum;

__global__ void k_zero() {
    if (threadIdx.x == 0) g_spksum = 0.0f;
}

// ---------------- per (b,c) mean over T --------------------------------------
__global__ void k_mean(const float* __restrict__ X) {
    int warp = (blockIdx.x * blockDim.x + threadIdx.x) >> 5;
    int lane = threadIdx.x & 31;
    if (warp >= BB * CC) return;
    const float* row = X + (size_t)warp * TN;
    float s = 0.f;
    for (int t = lane; t < TN; t += 32) s += row[t];
    #pragma unroll
    for (int o = 16; o; o >>= 1) s += __shfl_xor_sync(0xffffffffu, s, o);
    if (lane == 0) g_mean[warp] = s * (1.0f / TN);
}

// ---------------- cov = (X X^T - T m m^T)/(T-1) + 1e-4 I  (symmetric) --------
__global__ void k_cov(const float* __restrict__ X) {
    __shared__ float As[32][68];
    __shared__ float Bs[32][68];
    int b  = blockIdx.y;
    int blk = blockIdx.x;
    int i0 = (blk == 2) ? 64 : 0;
    int j0 = (blk == 0) ? 0 : 64;
    int tid = threadIdx.x;
    int tx = tid & 15, ty = tid >> 4;
    const float* Xb = X + (size_t)b * CC * TN;

    ull acc[4][2];
    #pragma unroll
    for (int a = 0; a < 4; a++) { acc[a][0] = 0ull; acc[a][1] = 0ull; }

    for (int k0 = 0; k0 < TN; k0 += 32) {
        for (int idx = tid; idx < 64 * 32; idx += 256) {
            int i = idx >> 5, kk = idx & 31;
            int k = k0 + kk;
            As[kk][i] = (k < TN) ? Xb[(size_t)(i0 + i) * TN + k] : 0.f;
            Bs[kk][i] = (k < TN) ? Xb[(size_t)(j0 + i) * TN + k] : 0.f;
        }
        __syncthreads();
        #pragma unroll 8
        for (int kk = 0; kk < 32; kk++) {
            float4 av = *reinterpret_cast<const float4*>(&As[kk][ty * 4]);
            const ull* bp = reinterpret_cast<const ull*>(&Bs[kk][tx * 4]);
            ull b0 = bp[0], b1 = bp[1];
            ull ad[4] = {d2(av.x), d2(av.y), d2(av.z), d2(av.w)};
            #pragma unroll
            for (int a = 0; a < 4; a++) {
                fma2(acc[a][0], ad[a], b0);
                fma2(acc[a][1], ad[a], b1);
            }
        }
        __syncthreads();
    }
    float* covb = g_cov + (size_t)b * CC * CC;
    #pragma unroll
    for (int a = 0; a < 4; a++) {
        int i = i0 + ty * 4 + a;
        float mi = g_mean[b * CC + i];
        float v4[4];
        up2(acc[a][0], v4[0], v4[1]);
        up2(acc[a][1], v4[2], v4[3]);
        #pragma unroll
        for (int c = 0; c < 4; c++) {
            int j = j0 + tx * 4 + c;
            float mj = g_mean[b * CC + j];
            float v = (v4[c] - (float)TN * mi * mj) * (1.0f / (TN - 1));
            if (i == j) v += 1e-4f;
            covb[(size_t)i * CC + j] = v;
            covb[(size_t)j * CC + i] = v;
        }
    }
}

// ---------------- matrix log (Mercator, symmetric trick) + row softmax -------
// log(A) = log(c) I - sum_{k=1..K} (I - A/c)^k / k,  c = 1.06 * trace/128
// M symmetric => P[r][kk] = P[kk][r]: both operands contiguous at uniform kk.
// Packed f32x2 along the j (column) dimension.
__global__ void __launch_bounds__(256, 1) k_logadj() {
    extern __shared__ float sm[];
    float* Ms = sm;
    float* Pa = sm + 16384;
    float* Pb = sm + 32768;
    __shared__ float red[128];
    __shared__ float csh[2];

    int b = blockIdx.x, tid = threadIdx.x;
    const float* cov = g_cov + (size_t)b * CC * CC;

    if (tid < 128) red[tid] = cov[tid * 129];
    __syncthreads();
    for (int o = 64; o; o >>= 1) {
        if (tid < o) red[tid] += red[tid + o];
        __syncthreads();
    }
    if (tid == 0) {
        float c = 1.06f * red[0] * (1.0f / 128.0f);
        csh[0] = 1.0f / c;
        csh[1] = logf(c);
    }
    __syncthreads();
    float invc = csh[0];

    for (int idx = tid; idx < 16384; idx += 256) {
        int i = idx >> 7, j = idx & 127;
        float m = ((i == j) ? 1.0f : 0.0f) - cov[idx] * invc;
        Ms[idx] = m;
        Pa[idx] = m;
    }
    __syncthreads();

    int ty = tid >> 4, tx = tid & 15;
    int r0 = ty * 8, c0 = tx * 8;

    ull La2[8][4];
    {
        ull negone = d2(-1.0f);
        #pragma unroll
        for (int i = 0; i < 8; i++) {
            const ull* mp = reinterpret_cast<const ull*>(&Ms[(r0 + i) * 128 + c0]);
            #pragma unroll
            for (int jj = 0; jj < 4; jj++) La2[i][jj] = mul2(mp[jj], negone);
        }
    }

    float* Po = Pa;
    float* Pn = Pb;
    for (int k = 2; k <= KTERMS; k++) {
        ull acc[8][4];
        #pragma unroll
        for (int i = 0; i < 8; i++)
            #pragma unroll
            for (int jj = 0; jj < 4; jj++) acc[i][jj] = 0ull;

        #pragma unroll 2
        for (int kk = 0; kk < 128; kk++) {
            float4 p0 = *reinterpret_cast<const float4*>(&Po[kk * 128 + r0]);
            float4 p1 = *reinterpret_cast<const float4*>(&Po[kk * 128 + r0 + 4]);
            const ull* mp = reinterpret_cast<const ull*>(&Ms[kk * 128 + c0]);
            ull m0 = mp[0], m1 = mp[1], m2 = mp[2], m3 = mp[3];
            ull pd[8] = {d2(p0.x), d2(p0.y), d2(p0.z), d2(p0.w),
                         d2(p1.x), d2(p1.y), d2(p1.z), d2(p1.w)};
            #pragma unroll
            for (int i = 0; i < 8; i++) {
                fma2(acc[i][0], pd[i], m0);
                fma2(acc[i][1], pd[i], m1);
                fma2(acc[i][2], pd[i], m2);
                fma2(acc[i][3], pd[i], m3);
            }
        }
        ull nik = d2(-1.0f / (float)k);
        #pragma unroll
        for (int i = 0; i < 8; i++) {
            ull* pnp = reinterpret_cast<ull*>(&Pn[(r0 + i) * 128 + c0]);
            #pragma unroll
            for (int jj = 0; jj < 4; jj++) {
                pnp[jj] = acc[i][jj];
                fma2(La2[i][jj], acc[i][jj], nik);
            }
        }
        __syncthreads();
        float* tmp = Po; Po = Pn; Pn = tmp;
    }

    // unpack, add log(c) on diagonal, row softmax over 16 tx lanes
    float logc = csh[1];
    #pragma unroll
    for (int i = 0; i < 8; i++) {
        float La[8];
        #pragma unroll
        for (int jj = 0; jj < 4; jj++) up2(La2[i][jj], La[2 * jj], La[2 * jj + 1]);
        int dj = (r0 + i) - c0;
        if (dj >= 0 && dj < 8) La[dj] += logc;

        float mx = -1e30f;
        #pragma unroll
        for (int j = 0; j < 8; j++) mx = fmaxf(mx, La[j]);
        #pragma unroll
        for (int o = 1; o < 16; o <<= 1) mx = fmaxf(mx, __shfl_xor_sync(0xffffffffu, mx, o));
        float e[8], s = 0.f;
        #pragma unroll
        for (int j = 0; j < 8; j++) { e[j] = expf(La[j] - mx); s += e[j]; }
        #pragma unroll
        for (int o = 1; o < 16; o <<= 1) s += __shfl_xor_sync(0xffffffffu, s, o);
        float inv = 1.0f / s;
        float* outp = g_adj + ((size_t)b * 128 + r0 + i) * 128 + c0;
        *reinterpret_cast<float4*>(outp) =
            make_float4(e[0] * inv, e[1] * inv, e[2] * inv, e[3] * inv);
        *reinterpret_cast<float4*>(outp + 4) =
            make_float4(e[4] * inv, e[5] * inv, e[6] * inv, e[7] * inv);
    }
}

// ---------------- conv1 (C=128 -> F=64, dil 1) + LN + relu + res1 ------------
// thread tile: 4 t x 8 f, packed f32x2 along f
__global__ void __launch_bounds__(256, 1)
k_conv1(const float* __restrict__ X,
        const float* __restrict__ w1, const float* __restrict__ b1,
        const float* __restrict__ lns, const float* __restrict__ lnb,
        const float* __restrict__ rw, const float* __restrict__ rb) {
    extern __shared__ float sm[];
    float* Xs = sm;                       // 128 x 132 (130 used)
    float* Ws = sm + 128 * 132;           // 3*128*64
    float* Rs = Ws + 3 * 128 * 64;        // 128*64
    int b = blockIdx.y;
    int t0 = blockIdx.x * 128;
    int tid = threadIdx.x;
    const float* Xb = X + (size_t)b * CC * TN;

    for (int idx = tid; idx < 128 * 130; idx += 256) {
        int c = idx / 130, u = idx % 130;
        int t = t0 - 1 + u;
        Xs[c * 132 + u] = (t >= 0 && t < TN) ? Xb[(size_t)c * TN + t] : 0.f;
    }
    for (int idx = tid; idx < 3 * 128 * 64; idx += 256) Ws[idx] = w1[idx];
    for (int idx = tid; idx < 128 * 64; idx += 256) Rs[idx] = rw[idx];
    __syncthreads();

    int tg = tid >> 3, fg = tid & 7;
    int f0 = fg * 8;
    int u0 = tg * 4;

    float ls[8], lb[8];
    ull acc[4][4], racc[4][4];
    #pragma unroll
    for (int jj = 0; jj < 4; jj++) {
        ull bj = pk2(b1[f0 + 2 * jj], b1[f0 + 2 * jj + 1]);
        ull rj = pk2(rb[f0 + 2 * jj], rb[f0 + 2 * jj + 1]);
        #pragma unroll
        for (int i = 0; i < 4; i++) { acc[i][jj] = bj; racc[i][jj] = rj; }
    }
    #pragma unroll
    for (int j = 0; j < 8; j++) { ls[j] = lns[f0 + j]; lb[j] = lnb[f0 + j]; }

    for (int c = 0; c < 128; c++) {
        ull xd[6];
        #pragma unroll
        for (int s = 0; s < 6; s++) xd[s] = d2(Xs[c * 132 + u0 + s]);
        const ull* w0p = reinterpret_cast<const ull*>(&Ws[c * 64 + f0]);
        const ull* w1p = reinterpret_cast<const ull*>(&Ws[8192 + c * 64 + f0]);
        const ull* w2p = reinterpret_cast<const ull*>(&Ws[16384 + c * 64 + f0]);
        const ull* rp  = reinterpret_cast<const ull*>(&Rs[c * 64 + f0]);
        #pragma unroll
        for (int jj = 0; jj < 4; jj++) {
            ull wa = w0p[jj], wb = w1p[jj], wc = w2p[jj], wr = rp[jj];
            #pragma unroll
            for (int i = 0; i < 4; i++) {
                fma2(acc[i][jj], xd[i], wa);
                fma2(acc[i][jj], xd[i + 1], wb);
                fma2(acc[i][jj], xd[i + 2], wc);
                fma2(racc[i][jj], xd[i + 1], wr);
            }
        }
    }

    #pragma unroll
    for (int i = 0; i < 4; i++) {
        float a8[8], r8[8];
        #pragma unroll
        for (int jj = 0; jj < 4; jj++) {
            up2(acc[i][jj], a8[2 * jj], a8[2 * jj + 1]);
            up2(racc[i][jj], r8[2 * jj], r8[2 * jj + 1]);
        }
        float s = 0.f, ss = 0.f;
        #pragma unroll
        for (int j = 0; j < 8; j++) { s += a8[j]; ss += a8[j] * a8[j]; }
        #pragma unroll
        for (int o = 1; o < 8; o <<= 1) {
            s  += __shfl_xor_sync(0xffffffffu, s, o);
            ss += __shfl_xor_sync(0xffffffffu, ss, o);
        }
        float m = s * (1.0f / 64.0f);
        float v = ss * (1.0f / 64.0f) - m * m;
        float rstd = rsqrtf(v + 1e-6f);
        int t = t0 + tg * 4 + i;
        if (t < TN) {
            float o8[8];
            #pragma unroll
            for (int j = 0; j < 8; j++) {
                float h = fmaxf((a8[j] - m) * rstd * ls[j] + lb[j], 0.f);
                o8[j] = h + r8[j];
            }
            float* op = g_t1 + ((size_t)b * TN + t) * 64 + f0;
            *reinterpret_cast<float4*>(op) = make_float4(o8[0], o8[1], o8[2], o8[3]);
            *reinterpret_cast<float4*>(op + 4) = make_float4(o8[4], o8[5], o8[6], o8[7]);
        }
    }
}

// ---------------- conv (F->F, dilation D) + LN + relu + identity res ---------
template <int D>
__global__ void __launch_bounds__(256, 2)
k_convres(const float* __restrict__ in,
          const float* __restrict__ w, const float* __restrict__ bias,
          const float* __restrict__ lns, const float* __restrict__ lnb,
          float* __restrict__ outp) {
    extern __shared__ float sm[];
    const int ROWS = 128 + 2 * D;
    float* Ts = sm;                 // ROWS x 65
    float* Ws = sm + ROWS * 65;     // 3*64*64
    int b = blockIdx.y;
    int t0 = blockIdx.x * 128;
    int tid = threadIdx.x;
    const float* inb = in + (size_t)b * TN * 64;

    for (int idx = tid; idx < ROWS * 64; idx += 256) {
        int u = idx >> 6, f = idx & 63;
        int t = t0 - D + u;
        Ts[u * 65 + f] = (t >= 0 && t < TN) ? inb[(size_t)t * 64 + f] : 0.f;
    }
    for (int idx = tid; idx < 3 * 64 * 64; idx += 256) Ws[idx] = w[idx];
    __syncthreads();

    int tg = tid >> 3, fg = tid & 7;
    int f0 = fg * 8;
    int u0 = tg * 4;

    float ls[8], lb[8];
    ull acc[4][4];
    #pragma unroll
    for (int jj = 0; jj < 4; jj++) {
        ull bj = pk2(bias[f0 + 2 * jj], bias[f0 + 2 * jj + 1]);
        #pragma unroll
        for (int i = 0; i < 4; i++) acc[i][jj] = bj;
    }
    #pragma unroll
    for (int j = 0; j < 8; j++) { ls[j] = lns[f0 + j]; lb[j] = lnb[f0 + j]; }

    for (int c = 0; c < 64; c++) {
        ull xd[2 * D + 4];
        #pragma unroll
        for (int s = 0; s < 2 * D + 4; s++) xd[s] = d2(Ts[(u0 + s) * 65 + c]);
        #pragma unroll
        for (int tap = 0; tap < 3; tap++) {
            const ull* wp = reinterpret_cast<const ull*>(&Ws[tap * 4096 + c * 64 + f0]);
            #pragma unroll
            for (int jj = 0; jj < 4; jj++) {
                ull wv = wp[jj];
                #pragma unroll
                for (int i = 0; i < 4; i++) fma2(acc[i][jj], xd[i + tap * D], wv);
            }
        }
    }

    #pragma unroll
    for (int i = 0; i < 4; i++) {
        float a8[8];
        #pragma unroll
        for (int jj = 0; jj < 4; jj++) up2(acc[i][jj], a8[2 * jj], a8[2 * jj + 1]);
        float s = 0.f, ss = 0.f;
        #pragma unroll
        for (int j = 0; j < 8; j++) { s += a8[j]; ss += a8[j] * a8[j]; }
        #pragma unroll
        for (int o = 1; o < 8; o <<= 1) {
            s  += __shfl_xor_sync(0xffffffffu, s, o);
            ss += __shfl_xor_sync(0xffffffffu, ss, o);
        }
        float m = s * (1.0f / 64.0f);
        float v = ss * (1.0f / 64.0f) - m * m;
        float rstd = rsqrtf(v + 1e-6f);
        int t = t0 + tg * 4 + i;
        if (t < TN) {
            float o8[8];
            #pragma unroll
            for (int j = 0; j < 8; j++) {
                float h = fmaxf((a8[j] - m) * rstd * ls[j] + lb[j], 0.f);
                o8[j] = h + Ts[(u0 + i + D) * 65 + f0 + j];
            }
            float* op = outp + ((size_t)b * TN + t) * 64 + f0;
            *reinterpret_cast<float4*>(op) = make_float4(o8[0], o8[1], o8[2], o8[3]);
            *reinterpret_cast<float4*>(op + 4) = make_float4(o8[4], o8[5], o8[6], o8[7]);
        }
    }
}

// ---------------- node_feats = X @ tcn_out, K split over 2 CTAs --------------
__global__ void k_nf(const float* __restrict__ X) {
    __shared__ float Xs[128][33];
    __shared__ float Ts[32][64];
    int half = blockIdx.x;
    int b = blockIdx.y;
    int tid = threadIdx.x;
    int c0 = (tid >> 4) * 8;
    int f0 = (tid & 15) * 4;
    ull acc[8][2];
    #pragma unroll
    for (int r = 0; r < 8; r++) { acc[r][0] = 0ull; acc[r][1] = 0ull; }

    const float* Xb = X + (size_t)b * CC * TN;
    const float* Tb = g_tcn + (size_t)b * TN * 64;
    int kbeg = half * 1000, kend = kbeg + 1000;

    for (int k0 = kbeg; k0 < kend; k0 += 32) {
        for (int idx = tid; idx < 128 * 32; idx += 256) {
            int c = idx >> 5, kk = idx & 31;
            int k = k0 + kk;
            Xs[c][kk] = (k < kend) ? Xb[(size_t)c * TN + k] : 0.f;
        }
        for (int idx = tid; idx < 32 * 64; idx += 256) {
            int kk = idx >> 6, f = idx & 63;
            int k = k0 + kk;
            Ts[kk][f] = (k < kend) ? Tb[(size_t)k * 64 + f] : 0.f;
        }
        __syncthreads();
        #pragma unroll 4
        for (int kk = 0; kk < 32; kk++) {
            const ull* tp = reinterpret_cast<const ull*>(&Ts[kk][f0]);
            ull t0v = tp[0], t1v = tp[1];
            #pragma unroll
            for (int r = 0; r < 8; r++) {
                ull xd = d2(Xs[c0 + r][kk]);
                fma2(acc[r][0], xd, t0v);
                fma2(acc[r][1], xd, t1v);
            }
        }
        __syncthreads();
    }
    #pragma unroll
    for (int r = 0; r < 8; r++) {
        float v4[4];
        up2(acc[r][0], v4[0], v4[1]);
        up2(acc[r][1], v4[2], v4[3]);
        float* o = g_nf + (size_t)half * BB * CC * FF + ((size_t)b * 128 + c0 + r) * 64 + f0;
        *reinterpret_cast<float4*>(o) = make_float4(v4[0], v4[1], v4[2], v4[3]);
    }
}

// ---------------- geo = relu(LN(adj @ node_feats)) ---------------------------
__global__ void k_geo(const float* __restrict__ lns, const float* __restrict__ lnb) {
    __shared__ float nfs[128 * 64];
    int b = blockIdx.x, tid = threadIdx.x;   // 128 threads
    for (int idx = tid; idx < 128 * 64; idx += 128)
        nfs[idx] = g_nf[(size_t)b * 8192 + idx] + g_nf[(size_t)BB * 8192 + (size_t)b * 8192 + idx];
    __syncthreads();

    const float* arow = g_adj + ((size_t)b * 128 + tid) * 128;
    ull acc[32];
    #pragma unroll
    for (int q = 0; q < 32; q++) acc[q] = 0ull;
    for (int j = 0; j < 128; j++) {
        ull a = d2(arow[j]);
        const ull* n2 = reinterpret_cast<const ull*>(&nfs[j * 64]);
        #pragma unroll
        for (int q = 0; q < 32; q++) fma2(acc[q], a, n2[q]);
    }
    float av[64];
    #pragma unroll
    for (int q = 0; q < 32; q++) up2(acc[q], av[2 * q], av[2 * q + 1]);
    float s = 0.f, ss = 0.f;
    #pragma unroll
    for (int j = 0; j < 64; j++) { s += av[j]; ss += av[j] * av[j]; }
    float m = s * (1.0f / 64.0f);
    float v = ss * (1.0f / 64.0f) - m * m;
    float rstd = rsqrtf(v + 1e-6f);
    float* o = g_geo + ((size_t)b * 128 + tid) * 64;
    #pragma unroll
    for (int j = 0; j < 64; j++)
        o[j] = fmaxf((av[j] - m) * rstd * lns[j] + lnb[j], 0.f);
}

// ---------------- decay GEMV partials: 4 K-chunks per batch row --------------
__global__ void k_decay(const float* __restrict__ dw) {
    __shared__ float gs[2048];
    int part = blockIdx.x, b = blockIdx.y;
    int tid = threadIdx.x;  // 128 threads
    int kbeg = part * 2048;
    for (int idx = tid; idx < 2048; idx += 128)
        gs[idx] = g_geo[(size_t)b * 8192 + kbeg + idx];
    __syncthreads();
    float a0 = 0.f, a1 = 0.f, a2 = 0.f, a3 = 0.f;
    for (int k = 0; k < 2048; k += 4) {
        a0 += gs[k + 0] * dw[(size_t)(kbeg + k + 0) * 128 + tid];
        a1 += gs[k + 1] * dw[(size_t)(kbeg + k + 1) * 128 + tid];
        a2 += gs[k + 2] * dw[(size_t)(kbeg + k + 2) * 128 + tid];
        a3 += gs[k + 3] * dw[(size_t)(kbeg + k + 3) * 128 + tid];
    }
    g_dpart[((size_t)part * BB + b) * HH + tid] = (a0 + a1) + (a2 + a3);
}

// ---------------- chunk-mean pool of tcn + seq_w GEMM ------------------------
__global__ void k_poolseq(const float* __restrict__ sw, const float* __restrict__ sb) {
    __shared__ float ps[64];
    int s = blockIdx.x, b = blockIdx.y, tid = threadIdx.x;  // 128 threads
    if (tid < 64) {
        const float* base = g_tcn + ((size_t)b * TN + s * 200) * 64 + tid;
        float a = 0.f;
        for (int t = 0; t < 200; t++) a += base[(size_t)t * 64];
        ps[tid] = a * (1.0f / 200.0f);
    }
    __syncthreads();
    float acc = sb[tid];
    #pragma unroll
    for (int f = 0; f < 64; f++) acc += ps[f] * sw[f * 128 + tid];
    g_seqin[((size_t)b * SEQN + s) * 128 + tid] = acc;
}

// ---------------- LIF scan + attention + heads -------------------------------
__global__ void k_lif(const float* __restrict__ db,
                      const float* __restrict__ aw, const float* __restrict__ ab,
                      const float* __restrict__ fw, const float* __restrict__ fb,
                      const float* __restrict__ ow, const float* __restrict__ ob,
                      float* __restrict__ dout) {
    __shared__ float red[128];
    __shared__ float attn[SEQN];
    __shared__ float featv[128];
    __shared__ float f2[64];
    int b = blockIdx.x, h = threadIdx.x;   // 128 threads

    float dacc = db[h]
        + g_dpart[((size_t)0 * BB + b) * HH + h]
        + g_dpart[((size_t)1 * BB + b) * HH + h]
        + g_dpart[((size_t)2 * BB + b) * HH + h]
        + g_dpart[((size_t)3 * BB + b) * HH + h];
    float d = 1.0f / (1.0f + expf(-dacc));

    float mem = 0.f, spsum = 0.f;
    float sp[SEQN];
    #pragma unroll
    for (int s = 0; s < SEQN; s++) {
        mem = mem * d + g_seqin[((size_t)b * SEQN + s) * 128 + h];
        float spike = (mem - 0.5f) > 0.f ? 1.0f : 0.0f;
        sp[s] = spike;
        spsum += spike;
        mem -= 0.5f * spike;
    }
    float awh = aw[h];
    for (int s = 0; s < SEQN; s++) {
        red[h] = sp[s] * awh;
        __syncthreads();
        for (int o = 64; o; o >>= 1) {
            if (h < o) red[h] += red[h + o];
            __syncthreads();
        }
        if (h == 0) attn[s] = red[0] + ab[0];
        __syncthreads();
    }
    red[h] = spsum;
    __syncthreads();
    for (int o = 64; o; o >>= 1) {
        if (h < o) red[h] += red[h + o];
        __syncthreads();
    }
    if (h == 0) atomicAdd(&g_spksum, red[0]);

    if (h == 0) {
        float mx = -1e30f;
        for (int s = 0; s < SEQN; s++) mx = fmaxf(mx, attn[s]);
        float ssum = 0.f;
        for (int s = 0; s < SEQN; s++) { attn[s] = expf(attn[s] - mx); ssum += attn[s]; }
        float inv = 1.0f / ssum;
        for (int s = 0; s < SEQN; s++) attn[s] *= inv;
    }
    __syncthreads();

    float fv = 0.f;
    #pragma unroll
    for (int s = 0; s < SEQN; s++) fv += sp[s] * attn[s];
    featv[h] = fv;
    __syncthreads();

    if (h < 64) {
        float acc = fb[h];
        for (int k = 0; k < 128; k++) acc += featv[k] * fw[k * 64 + h];
        f2[h] = fmaxf(acc, 0.f);
    }
    __syncthreads();
    if (h < 4) {
        float acc = ob[h];
        for (int j = 0; j < 64; j++) acc += f2[j] * ow[j * 4 + h];
        dout[b * 4 + h] = acc;
    }
}

__global__ void k_finmean(float* __restrict__ dout, int osz) {
    if (threadIdx.x == 0)
        dout[osz - 1] = g_spksum * (1.0f / ((float)BB * SEQN * HH));
}

// ---------------- launcher ----------------------------------------------------
extern "C" void kernel_launch(void* const* d_in, const int* in_sizes, int n_in,
                              void* d_out, int out_size) {
    const float* X    = (const float*)d_in[0];
    const float* c1w  = (const float*)d_in[1];
    const float* c1b  = (const float*)d_in[2];
    const float* l1s  = (const float*)d_in[3];
    const float* l1b  = (const float*)d_in[4];
    const float* r1w  = (const float*)d_in[5];
    const float* r1b  = (const float*)d_in[6];
    const float* c2w  = (const float*)d_in[7];
    const float* c2b  = (const float*)d_in[8];
    const float* l2s  = (const float*)d_in[9];
    const float* l2b  = (const float*)d_in[10];
    const float* c3w  = (const float*)d_in[11];
    const float* c3b  = (const float*)d_in[12];
    const float* l3s  = (const float*)d_in[13];
    const float* l3b  = (const float*)d_in[14];
    const float* lgs  = (const float*)d_in[15];
    const float* lgb  = (const float*)d_in[16];
    // d_in[17], d_in[18] = mix_w / mix_b : dead code in the reference
    const float* seqw = (const float*)d_in[19];
    const float* seqb = (const float*)d_in[20];
    const float* dw   = (const float*)d_in[21];
    const float* db   = (const float*)d_in[22];
    const float* aw   = (const float*)d_in[23];
    const float* ab   = (const float*)d_in[24];
    const float* fw   = (const float*)d_in[25];
    const float* fb   = (const float*)d_in[26];
    const float* ow   = (const float*)d_in[27];
    const float* ob   = (const float*)d_in[28];
    float* out = (float*)d_out;

    float *t1p, *t2p, *tcnp;
    cudaGetSymbolAddress((void**)&t1p, g_t1);
    cudaGetSymbolAddress((void**)&t2p, g_t2);
    cudaGetSymbolAddress((void**)&tcnp, g_tcn);

    size_t sm_log = (size_t)3 * 128 * 128 * sizeof(float);                     // 192 KB
    size_t sm_c1  = (size_t)(128 * 132 + 3 * 128 * 64 + 128 * 64) * sizeof(float);
    size_t sm_c2  = (size_t)(132 * 65 + 3 * 64 * 64) * sizeof(float);
    size_t sm_c3  = (size_t)(136 * 65 + 3 * 64 * 64) * sizeof(float);
    cudaFuncSetAttribute(k_logadj, cudaFuncAttributeMaxDynamicSharedMemorySize, (int)sm_log);
    cudaFuncSetAttribute(k_conv1, cudaFuncAttributeMaxDynamicSharedMemorySize, (int)sm_c1);
    cudaFuncSetAttribute(k_convres<2>, cudaFuncAttributeMaxDynamicSharedMemorySize, (int)sm_c2);
    cudaFuncSetAttribute(k_convres<4>, cudaFuncAttributeMaxDynamicSharedMemorySize, (int)sm_c3);

    k_zero<<<1, 32>>>();
    k_mean<<<(BB * CC * 32) / 256, 256>>>(X);
    {
        dim3 g(3, BB);
        k_cov<<<g, 256>>>(X);
    }
    k_logadj<<<BB, 256, sm_log>>>();
    {
        dim3 g(16, BB);
        k_conv1<<<g, 256, sm_c1>>>(X, c1w, c1b, l1s, l1b, r1w, r1b);
        k_convres<2><<<g, 256, sm_c2>>>(t1p, c2w, c2b, l2s, l2b, t2p);
        k_convres<4><<<g, 256, sm_c3>>>(t2p, c3w, c3b, l3s, l3b, tcnp);
    }
    {
        dim3 g(2, BB);
        k_nf<<<g, 256>>>(X);
    }
    k_geo<<<BB, 128>>>(lgs, lgb);
    {
        dim3 g(4, BB);
        k_decay<<<g, 128>>>(dw);
    }
    {
        dim3 g(SEQN, BB);
        k_poolseq<<<g, 128>>>(seqw, seqb);
    }
    k_lif<<<BB, 128>>>(db, aw, ab, fw, fb, ow, ob, out);
    k_finmean<<<1, 32>>>(out, out_size);
}

// round 6
// speedup vs baseline: 1.8426x; 1.1802x over previous
#include <cuda_runtime.h>
#include <math.h>

#define BB 128
#define CC 128
#define TN 2000
#define FF 64
#define HH 128
#define SEQN 10
#define KTERMS 14

typedef unsigned long long ull;

// ---- packed f32x2 helpers (sm_103a) -----------------------------------------
__device__ __forceinline__ ull d2(float x) {
    ull r; asm("mov.b64 %0, {%1, %1};" : "=l"(r) : "f"(x)); return r;
}
__device__ __forceinline__ ull pk2(float a, float b) {
    ull r; asm("mov.b64 %0, {%1, %2};" : "=l"(r) : "f"(a), "f"(b)); return r;
}
__device__ __forceinline__ void up2(ull v, float& a, float& b) {
    asm("mov.b64 {%0, %1}, %2;" : "=f"(a), "=f"(b) : "l"(v));
}
__device__ __forceinline__ void fma2(ull& d, ull a, ull b) {
    asm("fma.rn.f32x2 %0, %1, %2, %0;" : "+l"(d) : "l"(a), "l"(b));
}
__device__ __forceinline__ ull mul2(ull a, ull b) {
    ull r; asm("mul.rn.f32x2 %0, %1, %2;" : "=l"(r) : "l"(a), "l"(b)); return r;
}

// ---------------- scratch (device globals; no runtime allocation) -------------
__device__ float g_mean[BB*CC];
__device__ float g_cov[BB*CC*CC];
__device__ float g_adj[BB*CC*CC];
__device__ float g_t1[BB*TN*FF];
__device__ float g_t2[BB*TN*FF];
__device__ float g_tcn[BB*TN*FF];
__device__ float g_nf[2*BB*CC*FF];     // two K-partials, summed in k_geo
__device__ float g_geo[BB*CC*FF];
__device__ float g_dpart[4*BB*HH];     // decay GEMV partials
__device__ float g_seqin[BB*SEQN*HH];
__device__ float g_spksum;

// ---------------- per (b,c) mean over T (+ spike-sum zero) --------------------
__global__ void k_mean(const float* __restrict__ X) {
    if (blockIdx.x == 0 && threadIdx.x == 0) g_spksum = 0.0f;
    int warp = (blockIdx.x * blockDim.x + threadIdx.x) >> 5;
    int lane = threadIdx.x & 31;
    if (warp >= BB * CC) return;
    const float* row = X + (size_t)warp * TN;
    float s = 0.f;
    for (int t = lane; t < TN; t += 32) s += row[t];
    #pragma unroll
    for (int o = 16; o; o >>= 1) s += __shfl_xor_sync(0xffffffffu, s, o);
    if (lane == 0) g_mean[warp] = s * (1.0f / TN);
}

// ---------------- cov = (X X^T - T m m^T)/(T-1) + 1e-4 I  (symmetric) --------
__global__ void k_cov(const float* __restrict__ X) {
    __shared__ float As[32][68];
    __shared__ float Bs[32][68];
    int b  = blockIdx.y;
    int blk = blockIdx.x;
    int i0 = (blk == 2) ? 64 : 0;
    int j0 = (blk == 0) ? 0 : 64;
    int tid = threadIdx.x;
    int tx = tid & 15, ty = tid >> 4;
    const float* Xb = X + (size_t)b * CC * TN;

    ull acc[4][2];
    #pragma unroll
    for (int a = 0; a < 4; a++) { acc[a][0] = 0ull; acc[a][1] = 0ull; }

    for (int k0 = 0; k0 < TN; k0 += 32) {
        for (int idx = tid; idx < 64 * 32; idx += 256) {
            int i = idx >> 5, kk = idx & 31;
            int k = k0 + kk;
            As[kk][i] = (k < TN) ? Xb[(size_t)(i0 + i) * TN + k] : 0.f;
            Bs[kk][i] = (k < TN) ? Xb[(size_t)(j0 + i) * TN + k] : 0.f;
        }
        __syncthreads();
        #pragma unroll 8
        for (int kk = 0; kk < 32; kk++) {
            float4 av = *reinterpret_cast<const float4*>(&As[kk][ty * 4]);
            const ull* bp = reinterpret_cast<const ull*>(&Bs[kk][tx * 4]);
            ull b0 = bp[0], b1 = bp[1];
            ull ad[4] = {d2(av.x), d2(av.y), d2(av.z), d2(av.w)};
            #pragma unroll
            for (int a = 0; a < 4; a++) {
                fma2(acc[a][0], ad[a], b0);
                fma2(acc[a][1], ad[a], b1);
            }
        }
        __syncthreads();
    }
    float* covb = g_cov + (size_t)b * CC * CC;
    #pragma unroll
    for (int a = 0; a < 4; a++) {
        int i = i0 + ty * 4 + a;
        float mi = g_mean[b * CC + i];
        float v4[4];
        up2(acc[a][0], v4[0], v4[1]);
        up2(acc[a][1], v4[2], v4[3]);
        #pragma unroll
        for (int c = 0; c < 4; c++) {
            int j = j0 + tx * 4 + c;
            float mj = g_mean[b * CC + j];
            float v = (v4[c] - (float)TN * mi * mj) * (1.0f / (TN - 1));
            if (i == j) v += 1e-4f;
            covb[(size_t)i * CC + j] = v;
            covb[(size_t)j * CC + i] = v;
        }
    }
}

// ---------------- matrix log (Mercator, symmetric trick) + row softmax -------
__global__ void __launch_bounds__(256, 1) k_logadj() {
    extern __shared__ float sm[];
    float* Ms = sm;
    float* Pa = sm + 16384;
    float* Pb = sm + 32768;
    __shared__ float red[128];
    __shared__ float csh[2];

    int b = blockIdx.x, tid = threadIdx.x;
    const float* cov = g_cov + (size_t)b * CC * CC;

    if (tid < 128) red[tid] = cov[tid * 129];
    __syncthreads();
    for (int o = 64; o; o >>= 1) {
        if (tid < o) red[tid] += red[tid + o];
        __syncthreads();
    }
    if (tid == 0) {
        float c = 1.06f * red[0] * (1.0f / 128.0f);
        csh[0] = 1.0f / c;
        csh[1] = logf(c);
    }
    __syncthreads();
    float invc = csh[0];

    for (int idx = tid; idx < 16384; idx += 256) {
        int i = idx >> 7, j = idx & 127;
        float m = ((i == j) ? 1.0f : 0.0f) - cov[idx] * invc;
        Ms[idx] = m;
        Pa[idx] = m;
    }
    __syncthreads();

    int ty = tid >> 4, tx = tid & 15;
    int r0 = ty * 8, c0 = tx * 8;

    ull La2[8][4];
    {
        ull negone = d2(-1.0f);
        #pragma unroll
        for (int i = 0; i < 8; i++) {
            const ull* mp = reinterpret_cast<const ull*>(&Ms[(r0 + i) * 128 + c0]);
            #pragma unroll
            for (int jj = 0; jj < 4; jj++) La2[i][jj] = mul2(mp[jj], negone);
        }
    }

    float* Po = Pa;
    float* Pn = Pb;
    for (int k = 2; k <= KTERMS; k++) {
        ull acc[8][4];
        #pragma unroll
        for (int i = 0; i < 8; i++)
            #pragma unroll
            for (int jj = 0; jj < 4; jj++) acc[i][jj] = 0ull;

        #pragma unroll 2
        for (int kk = 0; kk < 128; kk++) {
            float4 p0 = *reinterpret_cast<const float4*>(&Po[kk * 128 + r0]);
            float4 p1 = *reinterpret_cast<const float4*>(&Po[kk * 128 + r0 + 4]);
            const ull* mp = reinterpret_cast<const ull*>(&Ms[kk * 128 + c0]);
            ull m0 = mp[0], m1 = mp[1], m2 = mp[2], m3 = mp[3];
            ull pd[8] = {d2(p0.x), d2(p0.y), d2(p0.z), d2(p0.w),
                         d2(p1.x), d2(p1.y), d2(p1.z), d2(p1.w)};
            #pragma unroll
            for (int i = 0; i < 8; i++) {
                fma2(acc[i][0], pd[i], m0);
                fma2(acc[i][1], pd[i], m1);
                fma2(acc[i][2], pd[i], m2);
                fma2(acc[i][3], pd[i], m3);
            }
        }
        ull nik = d2(-1.0f / (float)k);
        #pragma unroll
        for (int i = 0; i < 8; i++) {
            ull* pnp = reinterpret_cast<ull*>(&Pn[(r0 + i) * 128 + c0]);
            #pragma unroll
            for (int jj = 0; jj < 4; jj++) {
                pnp[jj] = acc[i][jj];
                fma2(La2[i][jj], acc[i][jj], nik);
            }
        }
        __syncthreads();
        float* tmp = Po; Po = Pn; Pn = tmp;
    }

    float logc = csh[1];
    #pragma unroll
    for (int i = 0; i < 8; i++) {
        float La[8];
        #pragma unroll
        for (int jj = 0; jj < 4; jj++) up2(La2[i][jj], La[2 * jj], La[2 * jj + 1]);
        int dj = (r0 + i) - c0;
        if (dj >= 0 && dj < 8) La[dj] += logc;

        float mx = -1e30f;
        #pragma unroll
        for (int j = 0; j < 8; j++) mx = fmaxf(mx, La[j]);
        #pragma unroll
        for (int o = 1; o < 16; o <<= 1) mx = fmaxf(mx, __shfl_xor_sync(0xffffffffu, mx, o));
        float e[8], s = 0.f;
        #pragma unroll
        for (int j = 0; j < 8; j++) { e[j] = expf(La[j] - mx); s += e[j]; }
        #pragma unroll
        for (int o = 1; o < 16; o <<= 1) s += __shfl_xor_sync(0xffffffffu, s, o);
        float inv = 1.0f / s;
        float* outp = g_adj + ((size_t)b * 128 + r0 + i) * 128 + c0;
        *reinterpret_cast<float4*>(outp) =
            make_float4(e[0] * inv, e[1] * inv, e[2] * inv, e[3] * inv);
        *reinterpret_cast<float4*>(outp + 4) =
            make_float4(e[4] * inv, e[5] * inv, e[6] * inv, e[7] * inv);
    }
}

// ---------------- conv1 (C=128 -> F=64, dil 1) + LN + relu + res1 ------------
// 512 threads, per-thread tile 2t x 8f (packed f32x2 along f)
__global__ void __launch_bounds__(512, 1)
k_conv1(const float* __restrict__ X,
        const float* __restrict__ w1, const float* __restrict__ b1,
        const float* __restrict__ lns, const float* __restrict__ lnb,
        const float* __restrict__ rw, const float* __restrict__ rb) {
    extern __shared__ float sm[];
    float* Xs = sm;                       // 128 x 132 (130 used)
    float* Ws = sm + 128 * 132;           // 3*128*64
    float* Rs = Ws + 3 * 128 * 64;        // 128*64
    int b = blockIdx.y;
    int t0 = blockIdx.x * 128;
    int tid = threadIdx.x;
    const float* Xb = X + (size_t)b * CC * TN;

    for (int idx = tid; idx < 128 * 130; idx += 512) {
        int c = idx / 130, u = idx % 130;
        int t = t0 - 1 + u;
        Xs[c * 132 + u] = (t >= 0 && t < TN) ? Xb[(size_t)c * TN + t] : 0.f;
    }
    for (int idx = tid; idx < 3 * 128 * 64; idx += 512) Ws[idx] = w1[idx];
    for (int idx = tid; idx < 128 * 64; idx += 512) Rs[idx] = rw[idx];
    __syncthreads();

    int tg = tid >> 3, fg = tid & 7;   // tg 0..63, fg 0..7
    int f0 = fg * 8;
    int u0 = tg * 2;

    float ls[8], lb[8];
    ull acc[2][4], racc[2][4];
    #pragma unroll
    for (int jj = 0; jj < 4; jj++) {
        ull bj = pk2(b1[f0 + 2 * jj], b1[f0 + 2 * jj + 1]);
        ull rj = pk2(rb[f0 + 2 * jj], rb[f0 + 2 * jj + 1]);
        #pragma unroll
        for (int i = 0; i < 2; i++) { acc[i][jj] = bj; racc[i][jj] = rj; }
    }
    #pragma unroll
    for (int j = 0; j < 8; j++) { ls[j] = lns[f0 + j]; lb[j] = lnb[f0 + j]; }

    for (int c = 0; c < 128; c++) {
        ull xd[4];
        #pragma unroll
        for (int s = 0; s < 4; s++) xd[s] = d2(Xs[c * 132 + u0 + s]);
        const ull* w0p = reinterpret_cast<const ull*>(&Ws[c * 64 + f0]);
        const ull* w1p = reinterpret_cast<const ull*>(&Ws[8192 + c * 64 + f0]);
        const ull* w2p = reinterpret_cast<const ull*>(&Ws[16384 + c * 64 + f0]);
        const ull* rp  = reinterpret_cast<const ull*>(&Rs[c * 64 + f0]);
        #pragma unroll
        for (int jj = 0; jj < 4; jj++) {
            ull wa = w0p[jj], wb = w1p[jj], wc = w2p[jj], wr = rp[jj];
            #pragma unroll
            for (int i = 0; i < 2; i++) {
                fma2(acc[i][jj], xd[i], wa);
                fma2(acc[i][jj], xd[i + 1], wb);
                fma2(acc[i][jj], xd[i + 2], wc);
                fma2(racc[i][jj], xd[i + 1], wr);
            }
        }
    }

    #pragma unroll
    for (int i = 0; i < 2; i++) {
        float a8[8], r8[8];
        #pragma unroll
        for (int jj = 0; jj < 4; jj++) {
            up2(acc[i][jj], a8[2 * jj], a8[2 * jj + 1]);
            up2(racc[i][jj], r8[2 * jj], r8[2 * jj + 1]);
        }
        float s = 0.f, ss = 0.f;
        #pragma unroll
        for (int j = 0; j < 8; j++) { s += a8[j]; ss += a8[j] * a8[j]; }
        #pragma unroll
        for (int o = 1; o < 8; o <<= 1) {
            s  += __shfl_xor_sync(0xffffffffu, s, o);
            ss += __shfl_xor_sync(0xffffffffu, ss, o);
        }
        float m = s * (1.0f / 64.0f);
        float v = ss * (1.0f / 64.0f) - m * m;
        float rstd = rsqrtf(v + 1e-6f);
        int t = t0 + u0 + i;
        if (t < TN) {
            float o8[8];
            #pragma unroll
            for (int j = 0; j < 8; j++) {
                float h = fmaxf((a8[j] - m) * rstd * ls[j] + lb[j], 0.f);
                o8[j] = h + r8[j];
            }
            float* op = g_t1 + ((size_t)b * TN + t) * 64 + f0;
            *reinterpret_cast<float4*>(op) = make_float4(o8[0], o8[1], o8[2], o8[3]);
            *reinterpret_cast<float4*>(op + 4) = make_float4(o8[4], o8[5], o8[6], o8[7]);
        }
    }
}

// ---------------- conv (F->F, dilation D) + LN + relu + identity res ---------
// 512 threads, per-thread tile 2t x 8f
template <int D>
__global__ void __launch_bounds__(512, 2)
k_convres(const float* __restrict__ in,
          const float* __restrict__ w, const float* __restrict__ bias,
          const float* __restrict__ lns, const float* __restrict__ lnb,
          float* __restrict__ outp) {
    extern __shared__ float sm[];
    const int ROWS = 128 + 2 * D;
    float* Ts = sm;                 // ROWS x 65
    float* Ws = sm + ROWS * 65;     // 3*64*64
    int b = blockIdx.y;
    int t0 = blockIdx.x * 128;
    int tid = threadIdx.x;
    const float* inb = in + (size_t)b * TN * 64;

    for (int idx = tid; idx < ROWS * 64; idx += 512) {
        int u = idx >> 6, f = idx & 63;
        int t = t0 - D + u;
        Ts[u * 65 + f] = (t >= 0 && t < TN) ? inb[(size_t)t * 64 + f] : 0.f;
    }
    for (int idx = tid; idx < 3 * 64 * 64; idx += 512) Ws[idx] = w[idx];
    __syncthreads();

    int tg = tid >> 3, fg = tid & 7;
    int f0 = fg * 8;
    int u0 = tg * 2;

    float ls[8], lb[8];
    ull acc[2][4];
    #pragma unroll
    for (int jj = 0; jj < 4; jj++) {
        ull bj = pk2(bias[f0 + 2 * jj], bias[f0 + 2 * jj + 1]);
        #pragma unroll
        for (int i = 0; i < 2; i++) acc[i][jj] = bj;
    }
    #pragma unroll
    for (int j = 0; j < 8; j++) { ls[j] = lns[f0 + j]; lb[j] = lnb[f0 + j]; }

    for (int c = 0; c < 64; c++) {
        ull xd[2 * D + 2];
        #pragma unroll
        for (int s = 0; s < 2 * D + 2; s++) xd[s] = d2(Ts[(u0 + s) * 65 + c]);
        #pragma unroll
        for (int tap = 0; tap < 3; tap++) {
            const ull* wp = reinterpret_cast<const ull*>(&Ws[tap * 4096 + c * 64 + f0]);
            #pragma unroll
            for (int jj = 0; jj < 4; jj++) {
                ull wv = wp[jj];
                #pragma unroll
                for (int i = 0; i < 2; i++) fma2(acc[i][jj], xd[i + tap * D], wv);
            }
        }
    }

    #pragma unroll
    for (int i = 0; i < 2; i++) {
        float a8[8];
        #pragma unroll
        for (int jj = 0; jj < 4; jj++) up2(acc[i][jj], a8[2 * jj], a8[2 * jj + 1]);
        float s = 0.f, ss = 0.f;
        #pragma unroll
        for (int j = 0; j < 8; j++) { s += a8[j]; ss += a8[j] * a8[j]; }
        #pragma unroll
        for (int o = 1; o < 8; o <<= 1) {
            s  += __shfl_xor_sync(0xffffffffu, s, o);
            ss += __shfl_xor_sync(0xffffffffu, ss, o);
        }
        float m = s * (1.0f / 64.0f);
        float v = ss * (1.0f / 64.0f) - m * m;
        float rstd = rsqrtf(v + 1e-6f);
        int t = t0 + u0 + i;
        if (t < TN) {
            float o8[8];
            #pragma unroll
            for (int j = 0; j < 8; j++) {
                float h = fmaxf((a8[j] - m) * rstd * ls[j] + lb[j], 0.f);
                o8[j] = h + Ts[(u0 + i + D) * 65 + f0 + j];
            }
            float* op = outp + ((size_t)b * TN + t) * 64 + f0;
            *reinterpret_cast<float4*>(op) = make_float4(o8[0], o8[1], o8[2], o8[3]);
            *reinterpret_cast<float4*>(op + 4) = make_float4(o8[4], o8[5], o8[6], o8[7]);
        }
    }
}

// ---------------- node_feats = X @ tcn_out, K split over 2 CTAs --------------
__global__ void k_nf(const float* __restrict__ X) {
    __shared__ float Xs[128][33];
    __shared__ float Ts[32][64];
    int half = blockIdx.x;
    int b = blockIdx.y;
    int tid = threadIdx.x;
    int c0 = (tid >> 4) * 8;
    int f0 = (tid & 15) * 4;
    ull acc[8][2];
    #pragma unroll
    for (int r = 0; r < 8; r++) { acc[r][0] = 0ull; acc[r][1] = 0ull; }

    const float* Xb = X + (size_t)b * CC * TN;
    const float* Tb = g_tcn + (size_t)b * TN * 64;
    int kbeg = half * 1000, kend = kbeg + 1000;

    for (int k0 = kbeg; k0 < kend; k0 += 32) {
        for (int idx = tid; idx < 128 * 32; idx += 256) {
            int c = idx >> 5, kk = idx & 31;
            int k = k0 + kk;
            Xs[c][kk] = (k < kend) ? Xb[(size_t)c * TN + k] : 0.f;
        }
        for (int idx = tid; idx < 32 * 64; idx += 256) {
            int kk = idx >> 6, f = idx & 63;
            int k = k0 + kk;
            Ts[kk][f] = (k < kend) ? Tb[(size_t)k * 64 + f] : 0.f;
        }
        __syncthreads();
        #pragma unroll 4
        for (int kk = 0; kk < 32; kk++) {
            const ull* tp = reinterpret_cast<const ull*>(&Ts[kk][f0]);
            ull t0v = tp[0], t1v = tp[1];
            #pragma unroll
            for (int r = 0; r < 8; r++) {
                ull xd = d2(Xs[c0 + r][kk]);
                fma2(acc[r][0], xd, t0v);
                fma2(acc[r][1], xd, t1v);
            }
        }
        __syncthreads();
    }
    #pragma unroll
    for (int r = 0; r < 8; r++) {
        float v4[4];
        up2(acc[r][0], v4[0], v4[1]);
        up2(acc[r][1], v4[2], v4[3]);
        float* o = g_nf + (size_t)half * BB * CC * FF + ((size_t)b * 128 + c0 + r) * 64 + f0;
        *reinterpret_cast<float4*>(o) = make_float4(v4[0], v4[1], v4[2], v4[3]);
    }
}

// ---------------- geo = relu(LN(adj @ node_feats)) ---------------------------
__global__ void k_geo(const float* __restrict__ lns, const float* __restrict__ lnb) {
    __shared__ float nfs[128 * 64];
    int b = blockIdx.x, tid = threadIdx.x;   // 128 threads
    for (int idx = tid; idx < 128 * 64; idx += 128)
        nfs[idx] = g_nf[(size_t)b * 8192 + idx] + g_nf[(size_t)BB * 8192 + (size_t)b * 8192 + idx];
    __syncthreads();

    const float* arow = g_adj + ((size_t)b * 128 + tid) * 128;
    ull acc[32];
    #pragma unroll
    for (int q = 0; q < 32; q++) acc[q] = 0ull;
    for (int j = 0; j < 128; j++) {
        ull a = d2(arow[j]);
        const ull* n2 = reinterpret_cast<const ull*>(&nfs[j * 64]);
        #pragma unroll
        for (int q = 0; q < 32; q++) fma2(acc[q], a, n2[q]);
    }
    float av[64];
    #pragma unroll
    for (int q = 0; q < 32; q++) up2(acc[q], av[2 * q], av[2 * q + 1]);
    float s = 0.f, ss = 0.f;
    #pragma unroll
    for (int j = 0; j < 64; j++) { s += av[j]; ss += av[j] * av[j]; }
    float m = s * (1.0f / 64.0f);
    float v = ss * (1.0f / 64.0f) - m * m;
    float rstd = rsqrtf(v + 1e-6f);
    float* o = g_geo + ((size_t)b * 128 + tid) * 64;
    #pragma unroll
    for (int j = 0; j < 64; j++)
        o[j] = fmaxf((av[j] - m) * rstd * lns[j] + lnb[j], 0.f);
}

// ---------------- decay GEMV partials: 4 K-chunks per batch row --------------
__global__ void k_decay(const float* __restrict__ dw) {
    __shared__ float gs[2048];
    int part = blockIdx.x, b = blockIdx.y;
    int tid = threadIdx.x;  // 128 threads
    int kbeg = part * 2048;
    for (int idx = tid; idx < 2048; idx += 128)
        gs[idx] = g_geo[(size_t)b * 8192 + kbeg + idx];
    __syncthreads();
    float a0 = 0.f, a1 = 0.f, a2 = 0.f, a3 = 0.f;
    for (int k = 0; k < 2048; k += 4) {
        a0 += gs[k + 0] * dw[(size_t)(kbeg + k + 0) * 128 + tid];
        a1 += gs[k + 1] * dw[(size_t)(kbeg + k + 1) * 128 + tid];
        a2 += gs[k + 2] * dw[(size_t)(kbeg + k + 2) * 128 + tid];
        a3 += gs[k + 3] * dw[(size_t)(kbeg + k + 3) * 128 + tid];
    }
    g_dpart[((size_t)part * BB + b) * HH + tid] = (a0 + a1) + (a2 + a3);
}

// ---------------- chunk-mean pool of tcn + seq_w GEMM ------------------------
__global__ void k_poolseq(const float* __restrict__ sw, const float* __restrict__ sb) {
    __shared__ float ps[64];
    int s = blockIdx.x, b = blockIdx.y, tid = threadIdx.x;  // 128 threads
    if (tid < 64) {
        const float* base = g_tcn + ((size_t)b * TN + s * 200) * 64 + tid;
        float a = 0.f;
        for (int t = 0; t < 200; t++) a += base[(size_t)t * 64];
        ps[tid] = a * (1.0f / 200.0f);
    }
    __syncthreads();
    float acc = sb[tid];
    #pragma unroll
    for (int f = 0; f < 64; f++) acc += ps[f] * sw[f * 128 + tid];
    g_seqin[((size_t)b * SEQN + s) * 128 + tid] = acc;
}

// ---------------- LIF scan + attention + heads -------------------------------
__global__ void k_lif(const float* __restrict__ db,
                      const float* __restrict__ aw, const float* __restrict__ ab,
                      const float* __restrict__ fw, const float* __restrict__ fb,
                      const float* __restrict__ ow, const float* __restrict__ ob,
                      float* __restrict__ dout) {
    __shared__ float red[128];
    __shared__ float attn[SEQN];
    __shared__ float featv[128];
    __shared__ float f2[64];
    int b = blockIdx.x, h = threadIdx.x;   // 128 threads

    float dacc = db[h]
        + g_dpart[((size_t)0 * BB + b) * HH + h]
        + g_dpart[((size_t)1 * BB + b) * HH + h]
        + g_dpart[((size_t)2 * BB + b) * HH + h]
        + g_dpart[((size_t)3 * BB + b) * HH + h];
    float d = 1.0f / (1.0f + expf(-dacc));

    float mem = 0.f, spsum = 0.f;
    float sp[SEQN];
    #pragma unroll
    for (int s = 0; s < SEQN; s++) {
        mem = mem * d + g_seqin[((size_t)b * SEQN + s) * 128 + h];
        float spike = (mem - 0.5f) > 0.f ? 1.0f : 0.0f;
        sp[s] = spike;
        spsum += spike;
        mem -= 0.5f * spike;
    }
    float awh = aw[h];
    for (int s = 0; s < SEQN; s++) {
        red[h] = sp[s] * awh;
        __syncthreads();
        for (int o = 64; o; o >>= 1) {
            if (h < o) red[h] += red[h + o];
            __syncthreads();
        }
        if (h == 0) attn[s] = red[0] + ab[0];
        __syncthreads();
    }
    red[h] = spsum;
    __syncthreads();
    for (int o = 64; o; o >>= 1) {
        if (h < o) red[h] += red[h + o];
        __syncthreads();
    }
    if (h == 0) atomicAdd(&g_spksum, red[0]);

    if (h == 0) {
        float mx = -1e30f;
        for (int s = 0; s < SEQN; s++) mx = fmaxf(mx, attn[s]);
        float ssum = 0.f;
        for (int s = 0; s < SEQN; s++) { attn[s] = expf(attn[s] - mx); ssum += attn[s]; }
        float inv = 1.0f / ssum;
        for (int s = 0; s < SEQN; s++) attn[s] *= inv;
    }
    __syncthreads();

    float fv = 0.f;
    #pragma unroll
    for (int s = 0; s < SEQN; s++) fv += sp[s] * attn[s];
    featv[h] = fv;
    __syncthreads();

    if (h < 64) {
        float acc = fb[h];
        for (int k = 0; k < 128; k++) acc += featv[k] * fw[k * 64 + h];
        f2[h] = fmaxf(acc, 0.f);
    }
    __syncthreads();
    if (h < 4) {
        float acc = ob[h];
        for (int j = 0; j < 64; j++) acc += f2[j] * ow[j * 4 + h];
        dout[b * 4 + h] = acc;
    }
}

__global__ void k_finmean(float* __restrict__ dout, int osz) {
    if (threadIdx.x == 0)
        dout[osz - 1] = g_spksum * (1.0f / ((float)BB * SEQN * HH));
}

// ---------------- launcher ----------------------------------------------------
extern "C" void kernel_launch(void* const* d_in, const int* in_sizes, int n_in,
                              void* d_out, int out_size) {
    const float* X    = (const float*)d_in[0];
    const float* c1w  = (const float*)d_in[1];
    const float* c1b  = (const float*)d_in[2];
    const float* l1s  = (const float*)d_in[3];
    const float* l1b  = (const float*)d_in[4];
    const float* r1w  = (const float*)d_in[5];
    const float* r1b  = (const float*)d_in[6];
    const float* c2w  = (const float*)d_in[7];
    const float* c2b  = (const float*)d_in[8];
    const float* l2s  = (const float*)d_in[9];
    const float* l2b  = (const float*)d_in[10];
    const float* c3w  = (const float*)d_in[11];
    const float* c3b  = (const float*)d_in[12];
    const float* l3s  = (const float*)d_in[13];
    const float* l3b  = (const float*)d_in[14];
    const float* lgs  = (const float*)d_in[15];
    const float* lgb  = (const float*)d_in[16];
    const float* seqw = (const float*)d_in[19];
    const float* seqb = (const float*)d_in[20];
    const float* dw   = (const float*)d_in[21];
    const float* db   = (const float*)d_in[22];
    const float* aw   = (const float*)d_in[23];
    const float* ab   = (const float*)d_in[24];
    const float* fw   = (const float*)d_in[25];
    const float* fb   = (const float*)d_in[26];
    const float* ow   = (const float*)d_in[27];
    const float* ob   = (const float*)d_in[28];
    float* out = (float*)d_out;

    float *t1p, *t2p, *tcnp;
    cudaGetSymbolAddress((void**)&t1p, g_t1);
    cudaGetSymbolAddress((void**)&t2p, g_t2);
    cudaGetSymbolAddress((void**)&tcnp, g_tcn);

    size_t sm_log = (size_t)3 * 128 * 128 * sizeof(float);                     // 192 KB
    size_t sm_c1  = (size_t)(128 * 132 + 3 * 128 * 64 + 128 * 64) * sizeof(float);
    size_t sm_c2  = (size_t)(132 * 65 + 3 * 64 * 64) * sizeof(float);
    size_t sm_c3  = (size_t)(136 * 65 + 3 * 64 * 64) * sizeof(float);
    cudaFuncSetAttribute(k_logadj, cudaFuncAttributeMaxDynamicSharedMemorySize, (int)sm_log);
    cudaFuncSetAttribute(k_conv1, cudaFuncAttributeMaxDynamicSharedMemorySize, (int)sm_c1);
    cudaFuncSetAttribute(k_convres<2>, cudaFuncAttributeMaxDynamicSharedMemorySize, (int)sm_c2);
    cudaFuncSetAttribute(k_convres<4>, cudaFuncAttributeMaxDynamicSharedMemorySize, (int)sm_c3);

    // Try to fork the (cov -> logadj) chain onto a second stream so it
    // overlaps with the conv chain. Fall back to fully serial if anything
    // fails. Events/stream are created per call (few calls total) and NOT
    // destroyed, to avoid invalidating the captured graph topology.
    cudaStream_t s2 = 0;
    cudaEvent_t e1 = 0, e2 = 0;
    bool fork = true;
    if (cudaStreamCreateWithFlags(&s2, cudaStreamNonBlocking) != cudaSuccess) fork = false;
    if (fork && cudaEventCreateWithFlags(&e1, cudaEventDisableTiming) != cudaSuccess) fork = false;
    if (fork && cudaEventCreateWithFlags(&e2, cudaEventDisableTiming) != cudaSuccess) fork = false;

    k_mean<<<(BB * CC * 32) / 256, 256>>>(X);

    if (fork) {
        cudaEventRecord(e1, 0);
        cudaStreamWaitEvent(s2, e1, 0);
        { dim3 g(3, BB); k_cov<<<g, 256, 0, s2>>>(X); }
        k_logadj<<<BB, 256, sm_log, s2>>>();
        cudaEventRecord(e2, s2);
    } else {
        { dim3 g(3, BB); k_cov<<<g, 256>>>(X); }
        k_logadj<<<BB, 256, sm_log>>>();
    }

    {
        dim3 g(16, BB);
        k_conv1<<<g, 512, sm_c1>>>(X, c1w, c1b, l1s, l1b, r1w, r1b);
        k_convres<2><<<g, 512, sm_c2>>>(t1p, c2w, c2b, l2s, l2b, t2p);
        k_convres<4><<<g, 512, sm_c3>>>(t2p, c3w, c3b, l3s, l3b, tcnp);
    }
    {
        dim3 g(2, BB);
        k_nf<<<g, 256>>>(X);
    }
    {
        dim3 g(SEQN, BB);
        k_poolseq<<<g, 128>>>(seqw, seqb);
    }

    if (fork) cudaStreamWaitEvent(0, e2, 0);   // join: geo needs adj

    k_geo<<<BB, 128>>>(lgs, lgb);
    {
        dim3 g(4, BB);
        k_decay<<<g, 128>>>(dw);
    }
    k_lif<<<BB, 128>>>(db, aw, ab, fw, fb, ow, ob, out);
    k_finmean<<<1, 32>>>(out, out_size);
}

// round 7
// speedup vs baseline: 2.3595x; 1.2805x over previous
#include <cuda_runtime.h>
#include <math.h>

#define BB 128
#define CC 128
#define TN 2000
#define FF 64
#define HH 128
#define SEQN 10
#define KTERMS 14

typedef unsigned long long ull;

// ---- packed f32x2 helpers (sm_103a) -----------------------------------------
__device__ __forceinline__ ull d2(float x) {
    ull r; asm("mov.b64 %0, {%1, %1};" : "=l"(r) : "f"(x)); return r;
}
__device__ __forceinline__ ull pk2(float a, float b) {
    ull r; asm("mov.b64 %0, {%1, %2};" : "=l"(r) : "f"(a), "f"(b)); return r;
}
__device__ __forceinline__ void up2(ull v, float& a, float& b) {
    asm("mov.b64 {%0, %1}, %2;" : "=f"(a), "=f"(b) : "l"(v));
}
__device__ __forceinline__ void fma2(ull& d, ull a, ull b) {
    asm("fma.rn.f32x2 %0, %1, %2, %0;" : "+l"(d) : "l"(a), "l"(b));
}
__device__ __forceinline__ ull mul2(ull a, ull b) {
    ull r; asm("mul.rn.f32x2 %0, %1, %2;" : "=l"(r) : "l"(a), "l"(b)); return r;
}

// ---------------- scratch (device globals; no runtime allocation) -------------
__device__ float g_mean[BB*CC];
__device__ float g_cov[BB*CC*CC];
__device__ float g_adj[BB*CC*CC];
__device__ float g_res[BB*TN*FF];
__device__ float g_t1[BB*TN*FF];
__device__ float g_t2[BB*TN*FF];
__device__ float g_tcn[BB*TN*FF];
__device__ float g_nf[2*BB*CC*FF];
__device__ float g_geo[BB*CC*FF];
__device__ float g_dpart[4*BB*HH];
__device__ float g_seqin[BB*SEQN*HH];
__device__ float g_spksum;

// ---------------- per (b,c) mean over T (+ spike-sum zero) --------------------
__global__ void k_mean(const float* __restrict__ X) {
    if (blockIdx.x == 0 && threadIdx.x == 0) g_spksum = 0.0f;
    int warp = (blockIdx.x * blockDim.x + threadIdx.x) >> 5;
    int lane = threadIdx.x & 31;
    if (warp >= BB * CC) return;
    const float* row = X + (size_t)warp * TN;
    float s = 0.f;
    for (int t = lane; t < TN; t += 32) s += row[t];
    #pragma unroll
    for (int o = 16; o; o >>= 1) s += __shfl_xor_sync(0xffffffffu, s, o);
    if (lane == 0) g_mean[warp] = s * (1.0f / TN);
}

// ---------------- cov: one CTA per batch, 8x8 reg tiles, shared k-tile -------
__global__ void __launch_bounds__(256, 1) k_cov(const float* __restrict__ X) {
    __shared__ float Xs[32 * 130];   // [kk][i], stride 130
    __shared__ float mn[128];
    int b = blockIdx.x, tid = threadIdx.x;
    if (tid < 128) mn[tid] = g_mean[b * CC + tid];
    const float* Xb = X + (size_t)b * CC * TN;

    int ty = tid >> 4, tx = tid & 15;
    int r0 = ty * 8, c0 = tx * 8;
    int kkl = tid & 31, iw = tid >> 5;   // load mapping

    ull acc[8][4];
    #pragma unroll
    for (int i = 0; i < 8; i++)
        #pragma unroll
        for (int jj = 0; jj < 4; jj++) acc[i][jj] = 0ull;

    for (int k0 = 0; k0 < TN; k0 += 32) {
        int k = k0 + kkl;
        bool ok = (k < TN);
        #pragma unroll 4
        for (int i = iw; i < 128; i += 8)
            Xs[kkl * 130 + i] = ok ? Xb[(size_t)i * TN + k] : 0.f;
        __syncthreads();
        #pragma unroll 4
        for (int kk = 0; kk < 32; kk++) {
            const float* row = &Xs[kk * 130];
            const ull* ap = reinterpret_cast<const ull*>(row + r0);
            const ull* bp = reinterpret_cast<const ull*>(row + c0);
            ull b0 = bp[0], b1 = bp[1], b2 = bp[2], b3 = bp[3];
            float a8[8];
            up2(ap[0], a8[0], a8[1]); up2(ap[1], a8[2], a8[3]);
            up2(ap[2], a8[4], a8[5]); up2(ap[3], a8[6], a8[7]);
            #pragma unroll
            for (int i = 0; i < 8; i++) {
                ull ad = d2(a8[i]);
                fma2(acc[i][0], ad, b0);
                fma2(acc[i][1], ad, b1);
                fma2(acc[i][2], ad, b2);
                fma2(acc[i][3], ad, b3);
            }
        }
        __syncthreads();
    }

    float* covb = g_cov + (size_t)b * CC * CC;
    #pragma unroll
    for (int i = 0; i < 8; i++) {
        int gi = r0 + i;
        float mi = mn[gi];
        float v8[8];
        #pragma unroll
        for (int jj = 0; jj < 4; jj++) up2(acc[i][jj], v8[2 * jj], v8[2 * jj + 1]);
        #pragma unroll
        for (int j = 0; j < 8; j++) {
            int gj = c0 + j;
            float v = (v8[j] - (float)TN * mi * mn[gj]) * (1.0f / (TN - 1));
            if (gi == gj) v += 1e-4f;
            v8[j] = v;
        }
        float* op = covb + (size_t)gi * CC + c0;
        *reinterpret_cast<float4*>(op) = make_float4(v8[0], v8[1], v8[2], v8[3]);
        *reinterpret_cast<float4*>(op + 4) = make_float4(v8[4], v8[5], v8[6], v8[7]);
    }
}

// ---------------- matrix log (Mercator, symmetric) + row softmax -------------
__global__ void __launch_bounds__(256, 1) k_logadj() {
    extern __shared__ float sm[];
    float* Ms = sm;
    float* Pa = sm + 16384;
    float* Pb = sm + 32768;
    __shared__ float red[128];
    __shared__ float csh[2];

    int b = blockIdx.x, tid = threadIdx.x;
    const float* cov = g_cov + (size_t)b * CC * CC;

    if (tid < 128) red[tid] = cov[tid * 129];
    __syncthreads();
    for (int o = 64; o; o >>= 1) {
        if (tid < o) red[tid] += red[tid + o];
        __syncthreads();
    }
    if (tid == 0) {
        float c = 1.06f * red[0] * (1.0f / 128.0f);
        csh[0] = 1.0f / c;
        csh[1] = logf(c);
    }
    __syncthreads();
    float invc = csh[0];

    for (int idx = tid; idx < 16384; idx += 256) {
        int i = idx >> 7, j = idx & 127;
        float m = ((i == j) ? 1.0f : 0.0f) - cov[idx] * invc;
        Ms[idx] = m;
        Pa[idx] = m;
    }
    __syncthreads();

    int ty = tid >> 4, tx = tid & 15;
    int r0 = ty * 8, c0 = tx * 8;

    ull La2[8][4];
    {
        ull negone = d2(-1.0f);
        #pragma unroll
        for (int i = 0; i < 8; i++) {
            const ull* mp = reinterpret_cast<const ull*>(&Ms[(r0 + i) * 128 + c0]);
            #pragma unroll
            for (int jj = 0; jj < 4; jj++) La2[i][jj] = mul2(mp[jj], negone);
        }
    }

    float* Po = Pa;
    float* Pn = Pb;
    for (int k = 2; k <= KTERMS; k++) {
        ull acc[8][4];
        #pragma unroll
        for (int i = 0; i < 8; i++)
            #pragma unroll
            for (int jj = 0; jj < 4; jj++) acc[i][jj] = 0ull;

        #pragma unroll 2
        for (int kk = 0; kk < 128; kk++) {
            float4 p0 = *reinterpret_cast<const float4*>(&Po[kk * 128 + r0]);
            float4 p1 = *reinterpret_cast<const float4*>(&Po[kk * 128 + r0 + 4]);
            const ull* mp = reinterpret_cast<const ull*>(&Ms[kk * 128 + c0]);
            ull m0 = mp[0], m1 = mp[1], m2 = mp[2], m3 = mp[3];
            ull pd[8] = {d2(p0.x), d2(p0.y), d2(p0.z), d2(p0.w),
                         d2(p1.x), d2(p1.y), d2(p1.z), d2(p1.w)};
            #pragma unroll
            for (int i = 0; i < 8; i++) {
                fma2(acc[i][0], pd[i], m0);
                fma2(acc[i][1], pd[i], m1);
                fma2(acc[i][2], pd[i], m2);
                fma2(acc[i][3], pd[i], m3);
            }
        }
        ull nik = d2(-1.0f / (float)k);
        #pragma unroll
        for (int i = 0; i < 8; i++) {
            ull* pnp = reinterpret_cast<ull*>(&Pn[(r0 + i) * 128 + c0]);
            #pragma unroll
            for (int jj = 0; jj < 4; jj++) {
                pnp[jj] = acc[i][jj];
                fma2(La2[i][jj], acc[i][jj], nik);
            }
        }
        __syncthreads();
        float* tmp = Po; Po = Pn; Pn = tmp;
    }

    float logc = csh[1];
    #pragma unroll
    for (int i = 0; i < 8; i++) {
        float La[8];
        #pragma unroll
        for (int jj = 0; jj < 4; jj++) up2(La2[i][jj], La[2 * jj], La[2 * jj + 1]);
        int dj = (r0 + i) - c0;
        if (dj >= 0 && dj < 8) La[dj] += logc;

        float mx = -1e30f;
        #pragma unroll
        for (int j = 0; j < 8; j++) mx = fmaxf(mx, La[j]);
        #pragma unroll
        for (int o = 1; o < 16; o <<= 1) mx = fmaxf(mx, __shfl_xor_sync(0xffffffffu, mx, o));
        float e[8], s = 0.f;
        #pragma unroll
        for (int j = 0; j < 8; j++) { e[j] = expf(La[j] - mx); s += e[j]; }
        #pragma unroll
        for (int o = 1; o < 16; o <<= 1) s += __shfl_xor_sync(0xffffffffu, s, o);
        float inv = 1.0f / s;
        float* outp = g_adj + ((size_t)b * 128 + r0 + i) * 128 + c0;
        *reinterpret_cast<float4*>(outp) =
            make_float4(e[0] * inv, e[1] * inv, e[2] * inv, e[3] * inv);
        *reinterpret_cast<float4*>(outp + 4) =
            make_float4(e[4] * inv, e[5] * inv, e[6] * inv, e[7] * inv);
    }
}

// ---------------- res GEMM: g_res = X_t @ rw + rb  ([B,T,64]) ----------------
__global__ void __launch_bounds__(256, 2)
k_res(const float* __restrict__ X, const float* __restrict__ rw,
      const float* __restrict__ rb) {
    extern __shared__ float sm[];
    float* Xs = sm;               // 128 c x 132 (128 t used)
    float* Rs = sm + 128 * 132;   // 128 x 64
    int b = blockIdx.y;
    int t0 = blockIdx.x * 128;
    int tid = threadIdx.x;
    int warp = tid >> 5, lane = tid & 31;
    const float* Xb = X + (size_t)b * CC * TN;

    for (int c = warp; c < 128; c += 8) {
        const float* src = Xb + (size_t)c * TN;
        for (int u = lane; u < 128; u += 32) {
            int t = t0 + u;
            Xs[c * 132 + u] = (t < TN) ? src[t] : 0.f;
        }
    }
    for (int idx = tid; idx < 128 * 64; idx += 256) Rs[idx] = rw[idx];
    __syncthreads();

    int tg = tid >> 3, fg = tid & 7;
    int f0 = fg * 8, u0 = tg * 4;

    ull acc[4][4];
    #pragma unroll
    for (int jj = 0; jj < 4; jj++) {
        ull bj = pk2(rb[f0 + 2 * jj], rb[f0 + 2 * jj + 1]);
        #pragma unroll
        for (int i = 0; i < 4; i++) acc[i][jj] = bj;
    }

    for (int c = 0; c < 128; c++) {
        ull xd[4];
        #pragma unroll
        for (int s = 0; s < 4; s++) xd[s] = d2(Xs[c * 132 + u0 + s]);
        const ull* rp = reinterpret_cast<const ull*>(&Rs[c * 64 + f0]);
        #pragma unroll
        for (int jj = 0; jj < 4; jj++) {
            ull wv = rp[jj];
            #pragma unroll
            for (int i = 0; i < 4; i++) fma2(acc[i][jj], xd[i], wv);
        }
    }

    #pragma unroll
    for (int i = 0; i < 4; i++) {
        int t = t0 + u0 + i;
        if (t < TN) {
            float v8[8];
            #pragma unroll
            for (int jj = 0; jj < 4; jj++) up2(acc[i][jj], v8[2 * jj], v8[2 * jj + 1]);
            float* op = g_res + ((size_t)b * TN + t) * 64 + f0;
            *reinterpret_cast<float4*>(op) = make_float4(v8[0], v8[1], v8[2], v8[3]);
            *reinterpret_cast<float4*>(op + 4) = make_float4(v8[4], v8[5], v8[6], v8[7]);
        }
    }
}

// ---------------- conv1 (C=128 -> F=64) + LN + relu + (precomputed res) ------
// 512 threads, per-thread 4t x 8f, t-tile 256. smem = 225 KB.
__global__ void __launch_bounds__(512, 1)
k_conv1(const float* __restrict__ X,
        const float* __restrict__ w1, const float* __restrict__ b1,
        const float* __restrict__ lns, const float* __restrict__ lnb) {
    extern __shared__ float sm[];
    float* Xs = sm;                 // 128 x 258
    float* Ws = sm + 128 * 258;     // 3*128*64
    int b = blockIdx.y;
    int t0 = blockIdx.x * 256;
    int tid = threadIdx.x;
    int warp = tid >> 5, lane = tid & 31;
    const float* Xb = X + (size_t)b * CC * TN;

    for (int c = warp; c < 128; c += 16) {
        const float* src = Xb + (size_t)c * TN;
        for (int u = lane; u < 258; u += 32) {
            int t = t0 - 1 + u;
            Xs[c * 258 + u] = (t >= 0 && t < TN) ? src[t] : 0.f;
        }
    }
    for (int idx = tid; idx < 3 * 128 * 64; idx += 512) Ws[idx] = w1[idx];
    __syncthreads();

    int tg = tid >> 3, fg = tid & 7;     // tg 0..63, fg 0..7
    int f0 = fg * 8, u0 = tg * 4;

    float ls[8], lb[8];
    ull acc[4][4];
    #pragma unroll
    for (int jj = 0; jj < 4; jj++) {
        ull bj = pk2(b1[f0 + 2 * jj], b1[f0 + 2 * jj + 1]);
        #pragma unroll
        for (int i = 0; i < 4; i++) acc[i][jj] = bj;
    }
    #pragma unroll
    for (int j = 0; j < 8; j++) { ls[j] = lns[f0 + j]; lb[j] = lnb[f0 + j]; }

    for (int c = 0; c < 128; c++) {
        ull xd[6];
        #pragma unroll
        for (int s = 0; s < 6; s++) xd[s] = d2(Xs[c * 258 + u0 + s]);
        #pragma unroll
        for (int tap = 0; tap < 3; tap++) {
            const ull* wp = reinterpret_cast<const ull*>(&Ws[tap * 8192 + c * 64 + f0]);
            #pragma unroll
            for (int jj = 0; jj < 4; jj++) {
                ull wv = wp[jj];
                #pragma unroll
                for (int i = 0; i < 4; i++) fma2(acc[i][jj], xd[i + tap], wv);
            }
        }
    }

    #pragma unroll
    for (int i = 0; i < 4; i++) {
        float a8[8];
        #pragma unroll
        for (int jj = 0; jj < 4; jj++) up2(acc[i][jj], a8[2 * jj], a8[2 * jj + 1]);
        float s = 0.f, ss = 0.f;
        #pragma unroll
        for (int j = 0; j < 8; j++) { s += a8[j]; ss += a8[j] * a8[j]; }
        #pragma unroll
        for (int o = 1; o < 8; o <<= 1) {
            s  += __shfl_xor_sync(0xffffffffu, s, o);
            ss += __shfl_xor_sync(0xffffffffu, ss, o);
        }
        float m = s * (1.0f / 64.0f);
        float v = ss * (1.0f / 64.0f) - m * m;
        float rstd = rsqrtf(v + 1e-6f);
        int t = t0 + u0 + i;
        if (t < TN) {
            const float* rp = g_res + ((size_t)b * TN + t) * 64 + f0;
            float4 r0v = *reinterpret_cast<const float4*>(rp);
            float4 r1v = *reinterpret_cast<const float4*>(rp + 4);
            float r8[8] = {r0v.x, r0v.y, r0v.z, r0v.w, r1v.x, r1v.y, r1v.z, r1v.w};
            float o8[8];
            #pragma unroll
            for (int j = 0; j < 8; j++) {
                float h = fmaxf((a8[j] - m) * rstd * ls[j] + lb[j], 0.f);
                o8[j] = h + r8[j];
            }
            float* op = g_t1 + ((size_t)b * TN + t) * 64 + f0;
            *reinterpret_cast<float4*>(op) = make_float4(o8[0], o8[1], o8[2], o8[3]);
            *reinterpret_cast<float4*>(op + 4) = make_float4(o8[4], o8[5], o8[6], o8[7]);
        }
    }
}

// ---------------- conv (F->F, dilation D) + LN + relu + identity res ---------
// 256 threads, per-thread 4t x 8f, t-tile 128, 2 CTAs/SM
template <int D>
__global__ void __launch_bounds__(256, 2)
k_convres(const float* __restrict__ in,
          const float* __restrict__ w, const float* __restrict__ bias,
          const float* __restrict__ lns, const float* __restrict__ lnb,
          float* __restrict__ outp) {
    extern __shared__ float sm[];
    const int ROWS = 128 + 2 * D;
    float* Ts = sm;                 // ROWS x 65
    float* Ws = sm + ROWS * 65;     // 3*64*64
    int b = blockIdx.y;
    int t0 = blockIdx.x * 128;
    int tid = threadIdx.x;
    const float* inb = in + (size_t)b * TN * 64;

    for (int idx = tid; idx < ROWS * 64; idx += 256) {
        int u = idx >> 6, f = idx & 63;
        int t = t0 - D + u;
        Ts[u * 65 + f] = (t >= 0 && t < TN) ? inb[(size_t)t * 64 + f] : 0.f;
    }
    for (int idx = tid; idx < 3 * 64 * 64; idx += 256) Ws[idx] = w[idx];
    __syncthreads();

    int tg = tid >> 3, fg = tid & 7;
    int f0 = fg * 8;
    int u0 = tg * 4;

    float ls[8], lb[8];
    ull acc[4][4];
    #pragma unroll
    for (int jj = 0; jj < 4; jj++) {
        ull bj = pk2(bias[f0 + 2 * jj], bias[f0 + 2 * jj + 1]);
        #pragma unroll
        for (int i = 0; i < 4; i++) acc[i][jj] = bj;
    }
    #pragma unroll
    for (int j = 0; j < 8; j++) { ls[j] = lns[f0 + j]; lb[j] = lnb[f0 + j]; }

    for (int c = 0; c < 64; c++) {
        ull xd[2 * D + 4];
        #pragma unroll
        for (int s = 0; s < 2 * D + 4; s++) xd[s] = d2(Ts[(u0 + s) * 65 + c]);
        #pragma unroll
        for (int tap = 0; tap < 3; tap++) {
            const ull* wp = reinterpret_cast<const ull*>(&Ws[tap * 4096 + c * 64 + f0]);
            #pragma unroll
            for (int jj = 0; jj < 4; jj++) {
                ull wv = wp[jj];
                #pragma unroll
                for (int i = 0; i < 4; i++) fma2(acc[i][jj], xd[i + tap * D], wv);
            }
        }
    }

    #pragma unroll
    for (int i = 0; i < 4; i++) {
        float a8[8];
        #pragma unroll
        for (int jj = 0; jj < 4; jj++) up2(acc[i][jj], a8[2 * jj], a8[2 * jj + 1]);
        float s = 0.f, ss = 0.f;
        #pragma unroll
        for (int j = 0; j < 8; j++) { s += a8[j]; ss += a8[j] * a8[j]; }
        #pragma unroll
        for (int o = 1; o < 8; o <<= 1) {
            s  += __shfl_xor_sync(0xffffffffu, s, o);
            ss += __shfl_xor_sync(0xffffffffu, ss, o);
        }
        float m = s * (1.0f / 64.0f);
        float v = ss * (1.0f / 64.0f) - m * m;
        float rstd = rsqrtf(v + 1e-6f);
        int t = t0 + u0 + i;
        if (t < TN) {
            float o8[8];
            #pragma unroll
            for (int j = 0; j < 8; j++) {
                float h = fmaxf((a8[j] - m) * rstd * ls[j] + lb[j], 0.f);
                o8[j] = h + Ts[(u0 + i + D) * 65 + f0 + j];
            }
            float* op = outp + ((size_t)b * TN + t) * 64 + f0;
            *reinterpret_cast<float4*>(op) = make_float4(o8[0], o8[1], o8[2], o8[3]);
            *reinterpret_cast<float4*>(op + 4) = make_float4(o8[4], o8[5], o8[6], o8[7]);
        }
    }
}

// ---------------- node_feats = X @ tcn_out, K split over 2 CTAs --------------
__global__ void k_nf(const float* __restrict__ X) {
    __shared__ float Xs[128][33];
    __shared__ float Ts[32][64];
    int half = blockIdx.x;
    int b = blockIdx.y;
    int tid = threadIdx.x;
    int c0 = (tid >> 4) * 8;
    int f0 = (tid & 15) * 4;
    ull acc[8][2];
    #pragma unroll
    for (int r = 0; r < 8; r++) { acc[r][0] = 0ull; acc[r][1] = 0ull; }

    const float* Xb = X + (size_t)b * CC * TN;
    const float* Tb = g_tcn + (size_t)b * TN * 64;
    int kbeg = half * 1000, kend = kbeg + 1000;

    for (int k0 = kbeg; k0 < kend; k0 += 32) {
        for (int idx = tid; idx < 128 * 32; idx += 256) {
            int c = idx >> 5, kk = idx & 31;
            int k = k0 + kk;
            Xs[c][kk] = (k < kend) ? Xb[(size_t)c * TN + k] : 0.f;
        }
        for (int idx = tid; idx < 32 * 64; idx += 256) {
            int kk = idx >> 6, f = idx & 63;
            int k = k0 + kk;
            Ts[kk][f] = (k < kend) ? Tb[(size_t)k * 64 + f] : 0.f;
        }
        __syncthreads();
        #pragma unroll 4
        for (int kk = 0; kk < 32; kk++) {
            const ull* tp = reinterpret_cast<const ull*>(&Ts[kk][f0]);
            ull t0v = tp[0], t1v = tp[1];
            #pragma unroll
            for (int r = 0; r < 8; r++) {
                ull xd = d2(Xs[c0 + r][kk]);
                fma2(acc[r][0], xd, t0v);
                fma2(acc[r][1], xd, t1v);
            }
        }
        __syncthreads();
    }
    #pragma unroll
    for (int r = 0; r < 8; r++) {
        float v4[4];
        up2(acc[r][0], v4[0], v4[1]);
        up2(acc[r][1], v4[2], v4[3]);
        float* o = g_nf + (size_t)half * BB * CC * FF + ((size_t)b * 128 + c0 + r) * 64 + f0;
        *reinterpret_cast<float4*>(o) = make_float4(v4[0], v4[1], v4[2], v4[3]);
    }
}

// ---------------- geo = relu(LN(adj @ node_feats)) ---------------------------
__global__ void k_geo(const float* __restrict__ lns, const float* __restrict__ lnb) {
    __shared__ float nfs[128 * 64];
    int b = blockIdx.x, tid = threadIdx.x;   // 128 threads
    for (int idx = tid; idx < 128 * 64; idx += 128)
        nfs[idx] = g_nf[(size_t)b * 8192 + idx] + g_nf[(size_t)BB * 8192 + (size_t)b * 8192 + idx];
    __syncthreads();

    const float* arow = g_adj + ((size_t)b * 128 + tid) * 128;
    ull acc[32];
    #pragma unroll
    for (int q = 0; q < 32; q++) acc[q] = 0ull;
    for (int j = 0; j < 128; j++) {
        ull a = d2(arow[j]);
        const ull* n2 = reinterpret_cast<const ull*>(&nfs[j * 64]);
        #pragma unroll
        for (int q = 0; q < 32; q++) fma2(acc[q], a, n2[q]);
    }
    float av[64];
    #pragma unroll
    for (int q = 0; q < 32; q++) up2(acc[q], av[2 * q], av[2 * q + 1]);
    float s = 0.f, ss = 0.f;
    #pragma unroll
    for (int j = 0; j < 64; j++) { s += av[j]; ss += av[j] * av[j]; }
    float m = s * (1.0f / 64.0f);
    float v = ss * (1.0f / 64.0f) - m * m;
    float rstd = rsqrtf(v + 1e-6f);
    float* o = g_geo + ((size_t)b * 128 + tid) * 64;
    #pragma unroll
    for (int j = 0; j < 64; j++)
        o[j] = fmaxf((av[j] - m) * rstd * lns[j] + lnb[j], 0.f);
}

// ---------------- decay GEMV partials: 4 K-chunks per batch row --------------
__global__ void k_decay(const float* __restrict__ dw) {
    __shared__ float gs[2048];
    int part = blockIdx.x, b = blockIdx.y;
    int tid = threadIdx.x;  // 128 threads
    int kbeg = part * 2048;
    for (int idx = tid; idx < 2048; idx += 128)
        gs[idx] = g_geo[(size_t)b * 8192 + kbeg + idx];
    __syncthreads();
    float a0 = 0.f, a1 = 0.f, a2 = 0.f, a3 = 0.f;
    for (int k = 0; k < 2048; k += 4) {
        a0 += gs[k + 0] * dw[(size_t)(kbeg + k + 0) * 128 + tid];
        a1 += gs[k + 1] * dw[(size_t)(kbeg + k + 1) * 128 + tid];
        a2 += gs[k + 2] * dw[(size_t)(kbeg + k + 2) * 128 + tid];
        a3 += gs[k + 3] * dw[(size_t)(kbeg + k + 3) * 128 + tid];
    }
    g_dpart[((size_t)part * BB + b) * HH + tid] = (a0 + a1) + (a2 + a3);
}

// ---------------- chunk-mean pool of tcn + seq_w GEMM ------------------------
__global__ void k_poolseq(const float* __restrict__ sw, const float* __restrict__ sb) {
    __shared__ float ps[64];
    int s = blockIdx.x, b = blockIdx.y, tid = threadIdx.x;  // 128 threads
    if (tid < 64) {
        const float* base = g_tcn + ((size_t)b * TN + s * 200) * 64 + tid;
        float a = 0.f;
        for (int t = 0; t < 200; t++) a += base[(size_t)t * 64];
        ps[tid] = a * (1.0f / 200.0f);
    }
    __syncthreads();
    float acc = sb[tid];
    #pragma unroll
    for (int f = 0; f < 64; f++) acc += ps[f] * sw[f * 128 + tid];
    g_seqin[((size_t)b * SEQN + s) * 128 + tid] = acc;
}

// ---------------- LIF scan + attention + heads -------------------------------
__global__ void k_lif(const float* __restrict__ db,
                      const float* __restrict__ aw, const float* __restrict__ ab,
                      const float* __restrict__ fw, const float* __restrict__ fb,
                      const float* __restrict__ ow, const float* __restrict__ ob,
                      float* __restrict__ dout) {
    __shared__ float red[128];
    __shared__ float attn[SEQN];
    __shared__ float featv[128];
    __shared__ float f2[64];
    int b = blockIdx.x, h = threadIdx.x;   // 128 threads

    float dacc = db[h]
        + g_dpart[((size_t)0 * BB + b) * HH + h]
        + g_dpart[((size_t)1 * BB + b) * HH + h]
        + g_dpart[((size_t)2 * BB + b) * HH + h]
        + g_dpart[((size_t)3 * BB + b) * HH + h];
    float d = 1.0f / (1.0f + expf(-dacc));

    float mem = 0.f, spsum = 0.f;
    float sp[SEQN];
    #pragma unroll
    for (int s = 0; s < SEQN; s++) {
        mem = mem * d + g_seqin[((size_t)b * SEQN + s) * 128 + h];
        float spike = (mem - 0.5f) > 0.f ? 1.0f : 0.0f;
        sp[s] = spike;
        spsum += spike;
        mem -= 0.5f * spike;
    }
    float awh = aw[h];
    for (int s = 0; s < SEQN; s++) {
        red[h] = sp[s] * awh;
        __syncthreads();
        for (int o = 64; o; o >>= 1) {
            if (h < o) red[h] += red[h + o];
            __syncthreads();
        }
        if (h == 0) attn[s] = red[0] + ab[0];
        __syncthreads();
    }
    red[h] = spsum;
    __syncthreads();
    for (int o = 64; o; o >>= 1) {
        if (h < o) red[h] += red[h + o];
        __syncthreads();
    }
    if (h == 0) atomicAdd(&g_spksum, red[0]);

    if (h == 0) {
        float mx = -1e30f;
        for (int s = 0; s < SEQN; s++) mx = fmaxf(mx, attn[s]);
        float ssum = 0.f;
        for (int s = 0; s < SEQN; s++) { attn[s] = expf(attn[s] - mx); ssum += attn[s]; }
        float inv = 1.0f / ssum;
        for (int s = 0; s < SEQN; s++) attn[s] *= inv;
    }
    __syncthreads();

    float fv = 0.f;
    #pragma unroll
    for (int s = 0; s < SEQN; s++) fv += sp[s] * attn[s];
    featv[h] = fv;
    __syncthreads();

    if (h < 64) {
        float acc = fb[h];
        for (int k = 0; k < 128; k++) acc += featv[k] * fw[k * 64 + h];
        f2[h] = fmaxf(acc, 0.f);
    }
    __syncthreads();
    if (h < 4) {
        float acc = ob[h];
        for (int j = 0; j < 64; j++) acc += f2[j] * ow[j * 4 + h];
        dout[b * 4 + h] = acc;
    }
}

__global__ void k_finmean(float* __restrict__ dout, int osz) {
    if (threadIdx.x == 0)
        dout[osz - 1] = g_spksum * (1.0f / ((float)BB * SEQN * HH));
}

// ---------------- launcher ----------------------------------------------------
extern "C" void kernel_launch(void* const* d_in, const int* in_sizes, int n_in,
                              void* d_out, int out_size) {
    const float* X    = (const float*)d_in[0];
    const float* c1w  = (const float*)d_in[1];
    const float* c1b  = (const float*)d_in[2];
    const float* l1s  = (const float*)d_in[3];
    const float* l1b  = (const float*)d_in[4];
    const float* r1w  = (const float*)d_in[5];
    const float* r1b  = (const float*)d_in[6];
    const float* c2w  = (const float*)d_in[7];
    const float* c2b  = (const float*)d_in[8];
    const float* l2s  = (const float*)d_in[9];
    const float* l2b  = (const float*)d_in[10];
    const float* c3w  = (const float*)d_in[11];
    const float* c3b  = (const float*)d_in[12];
    const float* l3s  = (const float*)d_in[13];
    const float* l3b  = (const float*)d_in[14];
    const float* lgs  = (const float*)d_in[15];
    const float* lgb  = (const float*)d_in[16];
    const float* seqw = (const float*)d_in[19];
    const float* seqb = (const float*)d_in[20];
    const float* dw   = (const float*)d_in[21];
    const float* db   = (const float*)d_in[22];
    const float* aw   = (const float*)d_in[23];
    const float* ab   = (const float*)d_in[24];
    const float* fw   = (const float*)d_in[25];
    const float* fb   = (const float*)d_in[26];
    const float* ow   = (const float*)d_in[27];
    const float* ob   = (const float*)d_in[28];
    float* out = (float*)d_out;

    float *t1p, *t2p, *tcnp;
    cudaGetSymbolAddress((void**)&t1p, g_t1);
    cudaGetSymbolAddress((void**)&t2p, g_t2);
    cudaGetSymbolAddress((void**)&tcnp, g_tcn);

    size_t sm_log = (size_t)3 * 128 * 128 * sizeof(float);                 // 192 KB
    size_t sm_c1  = (size_t)(128 * 258 + 3 * 128 * 64) * sizeof(float);    // 225 KB
    size_t sm_res = (size_t)(128 * 132 + 128 * 64) * sizeof(float);        // ~98 KB
    size_t sm_c2  = (size_t)(132 * 65 + 3 * 64 * 64) * sizeof(float);
    size_t sm_c3  = (size_t)(136 * 65 + 3 * 64 * 64) * sizeof(float);
    cudaFuncSetAttribute(k_logadj, cudaFuncAttributeMaxDynamicSharedMemorySize, (int)sm_log);
    cudaFuncSetAttribute(k_conv1, cudaFuncAttributeMaxDynamicSharedMemorySize, (int)sm_c1);
    cudaFuncSetAttribute(k_res, cudaFuncAttributeMaxDynamicSharedMemorySize, (int)sm_res);
    cudaFuncSetAttribute(k_convres<2>, cudaFuncAttributeMaxDynamicSharedMemorySize, (int)sm_c2);
    cudaFuncSetAttribute(k_convres<4>, cudaFuncAttributeMaxDynamicSharedMemorySize, (int)sm_c3);

    cudaStream_t s2 = 0;
    cudaEvent_t e1 = 0, e2 = 0;
    bool fork = true;
    if (cudaStreamCreateWithFlags(&s2, cudaStreamNonBlocking) != cudaSuccess) fork = false;
    if (fork && cudaEventCreateWithFlags(&e1, cudaEventDisableTiming) != cudaSuccess) fork = false;
    if (fork && cudaEventCreateWithFlags(&e2, cudaEventDisableTiming) != cudaSuccess) fork = false;

    k_mean<<<(BB * CC * 32) / 256, 256>>>(X);

    if (fork) {
        cudaEventRecord(e1, 0);
        cudaStreamWaitEvent(s2, e1, 0);
        k_cov<<<BB, 256, 0, s2>>>(X);
        k_logadj<<<BB, 256, sm_log, s2>>>();
        cudaEventRecord(e2, s2);
    } else {
        k_cov<<<BB, 256>>>(X);
        k_logadj<<<BB, 256, sm_log>>>();
    }

    {
        dim3 gr(16, BB);
        k_res<<<gr, 256, sm_res>>>(X, r1w, r1b);
        dim3 g1(8, BB);
        k_conv1<<<g1, 512, sm_c1>>>(X, c1w, c1b, l1s, l1b);
        dim3 g(16, BB);
        k_convres<2><<<g, 256, sm_c2>>>(t1p, c2w, c2b, l2s, l2b, t2p);
        k_convres<4><<<g, 256, sm_c3>>>(t2p, c3w, c3b, l3s, l3b, tcnp);
    }
    {
        dim3 g(2, BB);
        k_nf<<<g, 256>>>(X);
    }
    {
        dim3 g(SEQN, BB);
        k_poolseq<<<g, 128>>>(seqw, seqb);
    }

    if (fork) cudaStreamWaitEvent(0, e2, 0);

    k_geo<<<BB, 128>>>(lgs, lgb);
    {
        dim3 g(4, BB);
        k_decay<<<g, 128>>>(dw);
    }
    k_lif<<<BB, 128>>>(db, aw, ab, fw, fb, ow, ob, out);
    k_finmean<<<1, 32>>>(out, out_size);
}

// round 8
// speedup vs baseline: 2.5373x; 1.0754x over previous
#include <cuda_runtime.h>
#include <math.h>

#define BB 128
#define CC 128
#define TN 2000
#define FF 64
#define HH 128
#define SEQN 10
#define KTERMS 12

typedef unsigned long long ull;

// ---- packed f32x2 helpers (sm_103a) -----------------------------------------
__device__ __forceinline__ ull d2(float x) {
    ull r; asm("mov.b64 %0, {%1, %1};" : "=l"(r) : "f"(x)); return r;
}
__device__ __forceinline__ ull pk2(float a, float b) {
    ull r; asm("mov.b64 %0, {%1, %2};" : "=l"(r) : "f"(a), "f"(b)); return r;
}
__device__ __forceinline__ void up2(ull v, float& a, float& b) {
    asm("mov.b64 {%0, %1}, %2;" : "=f"(a), "=f"(b) : "l"(v));
}
__device__ __forceinline__ void fma2(ull& d, ull a, ull b) {
    asm("fma.rn.f32x2 %0, %1, %2, %0;" : "+l"(d) : "l"(a), "l"(b));
}
__device__ __forceinline__ ull mul2(ull a, ull b) {
    ull r; asm("mul.rn.f32x2 %0, %1, %2;" : "=l"(r) : "l"(a), "l"(b)); return r;
}

// ---------------- scratch (device globals; no runtime allocation) -------------
__device__ float g_mean[BB*CC];
__device__ float g_cov[BB*CC*CC];
__device__ float g_adj[BB*CC*CC];
__device__ float g_res[BB*TN*FF];
__device__ float g_t1[BB*TN*FF];
__device__ float g_t2[BB*TN*FF];
__device__ float g_tcn[BB*TN*FF];
__device__ float g_nf[2*BB*CC*FF];
__device__ float g_geo[BB*CC*FF];
__device__ float g_dpart[4*BB*HH];
__device__ float g_seqin[BB*SEQN*HH];
__device__ float g_spksum;

// ---------------- per (b,c) mean over T (+ spike-sum zero) --------------------
__global__ void k_mean(const float* __restrict__ X) {
    if (blockIdx.x == 0 && threadIdx.x == 0) g_spksum = 0.0f;
    int warp = (blockIdx.x * blockDim.x + threadIdx.x) >> 5;
    int lane = threadIdx.x & 31;
    if (warp >= BB * CC) return;
    const float* row = X + (size_t)warp * TN;
    float s = 0.f;
    for (int t = lane; t < TN; t += 32) s += row[t];
    #pragma unroll
    for (int o = 16; o; o >>= 1) s += __shfl_xor_sync(0xffffffffu, s, o);
    if (lane == 0) g_mean[warp] = s * (1.0f / TN);
}

// ---------------- cov: one CTA per batch, 8x8 reg tiles, shared k-tile -------
__global__ void __launch_bounds__(256, 1) k_cov(const float* __restrict__ X) {
    __shared__ float Xs[32 * 130];
    __shared__ float mn[128];
    int b = blockIdx.x, tid = threadIdx.x;
    if (tid < 128) mn[tid] = g_mean[b * CC + tid];
    const float* Xb = X + (size_t)b * CC * TN;

    int ty = tid >> 4, tx = tid & 15;
    int r0 = ty * 8, c0 = tx * 8;
    int kkl = tid & 31, iw = tid >> 5;

    ull acc[8][4];
    #pragma unroll
    for (int i = 0; i < 8; i++)
        #pragma unroll
        for (int jj = 0; jj < 4; jj++) acc[i][jj] = 0ull;

    for (int k0 = 0; k0 < TN; k0 += 32) {
        int k = k0 + kkl;
        bool ok = (k < TN);
        #pragma unroll 4
        for (int i = iw; i < 128; i += 8)
            Xs[kkl * 130 + i] = ok ? Xb[(size_t)i * TN + k] : 0.f;
        __syncthreads();
        #pragma unroll 4
        for (int kk = 0; kk < 32; kk++) {
            const float* row = &Xs[kk * 130];
            const ull* ap = reinterpret_cast<const ull*>(row + r0);
            const ull* bp = reinterpret_cast<const ull*>(row + c0);
            ull b0 = bp[0], b1 = bp[1], b2 = bp[2], b3 = bp[3];
            float a8[8];
            up2(ap[0], a8[0], a8[1]); up2(ap[1], a8[2], a8[3]);
            up2(ap[2], a8[4], a8[5]); up2(ap[3], a8[6], a8[7]);
            #pragma unroll
            for (int i = 0; i < 8; i++) {
                ull ad = d2(a8[i]);
                fma2(acc[i][0], ad, b0);
                fma2(acc[i][1], ad, b1);
                fma2(acc[i][2], ad, b2);
                fma2(acc[i][3], ad, b3);
            }
        }
        __syncthreads();
    }

    float* covb = g_cov + (size_t)b * CC * CC;
    #pragma unroll
    for (int i = 0; i < 8; i++) {
        int gi = r0 + i;
        float mi = mn[gi];
        float v8[8];
        #pragma unroll
        for (int jj = 0; jj < 4; jj++) up2(acc[i][jj], v8[2 * jj], v8[2 * jj + 1]);
        #pragma unroll
        for (int j = 0; j < 8; j++) {
            int gj = c0 + j;
            float v = (v8[j] - (float)TN * mi * mn[gj]) * (1.0f / (TN - 1));
            if (gi == gj) v += 1e-4f;
            v8[j] = v;
        }
        float* op = covb + (size_t)gi * CC + c0;
        *reinterpret_cast<float4*>(op) = make_float4(v8[0], v8[1], v8[2], v8[3]);
        *reinterpret_cast<float4*>(op + 4) = make_float4(v8[4], v8[5], v8[6], v8[7]);
    }
}

// ---------------- matrix log (Mercator, symmetric, single P buffer) ----------
// The per-thread acc registers hold the entire next power, so P is updated
// in place after a sync. smem = 128 KB -> convres CTAs can co-reside.
__global__ void __launch_bounds__(256, 1) k_logadj() {
    extern __shared__ float sm[];
    float* Ms = sm;
    float* Ps = sm + 16384;
    __shared__ float red[128];
    __shared__ float csh[2];

    int b = blockIdx.x, tid = threadIdx.x;
    const float* cov = g_cov + (size_t)b * CC * CC;

    if (tid < 128) red[tid] = cov[tid * 129];
    __syncthreads();
    for (int o = 64; o; o >>= 1) {
        if (tid < o) red[tid] += red[tid + o];
        __syncthreads();
    }
    if (tid == 0) {
        float c = 1.06f * red[0] * (1.0f / 128.0f);
        csh[0] = 1.0f / c;
        csh[1] = logf(c);
    }
    __syncthreads();
    float invc = csh[0];

    for (int idx = tid; idx < 16384; idx += 256) {
        int i = idx >> 7, j = idx & 127;
        float m = ((i == j) ? 1.0f : 0.0f) - cov[idx] * invc;
        Ms[idx] = m;
        Ps[idx] = m;
    }
    __syncthreads();

    int ty = tid >> 4, tx = tid & 15;
    int r0 = ty * 8, c0 = tx * 8;

    ull La2[8][4];
    {
        ull negone = d2(-1.0f);
        #pragma unroll
        for (int i = 0; i < 8; i++) {
            const ull* mp = reinterpret_cast<const ull*>(&Ms[(r0 + i) * 128 + c0]);
            #pragma unroll
            for (int jj = 0; jj < 4; jj++) La2[i][jj] = mul2(mp[jj], negone);
        }
    }

    for (int k = 2; k <= KTERMS; k++) {
        ull acc[8][4];
        #pragma unroll
        for (int i = 0; i < 8; i++)
            #pragma unroll
            for (int jj = 0; jj < 4; jj++) acc[i][jj] = 0ull;

        #pragma unroll 2
        for (int kk = 0; kk < 128; kk++) {
            float4 p0 = *reinterpret_cast<const float4*>(&Ps[kk * 128 + r0]);
            float4 p1 = *reinterpret_cast<const float4*>(&Ps[kk * 128 + r0 + 4]);
            const ull* mp = reinterpret_cast<const ull*>(&Ms[kk * 128 + c0]);
            ull m0 = mp[0], m1 = mp[1], m2 = mp[2], m3 = mp[3];
            ull pd[8] = {d2(p0.x), d2(p0.y), d2(p0.z), d2(p0.w),
                         d2(p1.x), d2(p1.y), d2(p1.z), d2(p1.w)};
            #pragma unroll
            for (int i = 0; i < 8; i++) {
                fma2(acc[i][0], pd[i], m0);
                fma2(acc[i][1], pd[i], m1);
                fma2(acc[i][2], pd[i], m2);
                fma2(acc[i][3], pd[i], m3);
            }
        }
        __syncthreads();   // all reads of Ps complete
        ull nik = d2(-1.0f / (float)k);
        #pragma unroll
        for (int i = 0; i < 8; i++) {
            ull* pnp = reinterpret_cast<ull*>(&Ps[(r0 + i) * 128 + c0]);
            #pragma unroll
            for (int jj = 0; jj < 4; jj++) {
                pnp[jj] = acc[i][jj];
                fma2(La2[i][jj], acc[i][jj], nik);
            }
        }
        __syncthreads();   // writes visible for next iteration
    }

    float logc = csh[1];
    #pragma unroll
    for (int i = 0; i < 8; i++) {
        float La[8];
        #pragma unroll
        for (int jj = 0; jj < 4; jj++) up2(La2[i][jj], La[2 * jj], La[2 * jj + 1]);
        int dj = (r0 + i) - c0;
        if (dj >= 0 && dj < 8) La[dj] += logc;

        float mx = -1e30f;
        #pragma unroll
        for (int j = 0; j < 8; j++) mx = fmaxf(mx, La[j]);
        #pragma unroll
        for (int o = 1; o < 16; o <<= 1) mx = fmaxf(mx, __shfl_xor_sync(0xffffffffu, mx, o));
        float e[8], s = 0.f;
        #pragma unroll
        for (int j = 0; j < 8; j++) { e[j] = expf(La[j] - mx); s += e[j]; }
        #pragma unroll
        for (int o = 1; o < 16; o <<= 1) s += __shfl_xor_sync(0xffffffffu, s, o);
        float inv = 1.0f / s;
        float* outp = g_adj + ((size_t)b * 128 + r0 + i) * 128 + c0;
        *reinterpret_cast<float4*>(outp) =
            make_float4(e[0] * inv, e[1] * inv, e[2] * inv, e[3] * inv);
        *reinterpret_cast<float4*>(outp + 4) =
            make_float4(e[4] * inv, e[5] * inv, e[6] * inv, e[7] * inv);
    }
}

// ---------------- res GEMM: g_res = X_t @ rw + rb  ([B,T,64]) ----------------
__global__ void __launch_bounds__(256, 2)
k_res(const float* __restrict__ X, const float* __restrict__ rw,
      const float* __restrict__ rb) {
    extern __shared__ float sm[];
    float* Xs = sm;               // 128 c x 132 (128 t used)
    float* Rs = sm + 128 * 132;   // 128 x 64
    int b = blockIdx.y;
    int t0 = blockIdx.x * 128;
    int tid = threadIdx.x;
    int warp = tid >> 5, lane = tid & 31;
    const float* Xb = X + (size_t)b * CC * TN;

    for (int c = warp; c < 128; c += 8) {
        const float* src = Xb + (size_t)c * TN + t0;
        int u = lane * 4;
        float4 v;
        if (t0 + u + 3 < TN) {
            v = *reinterpret_cast<const float4*>(src + u);
        } else {
            v.x = (t0 + u     < TN) ? src[u]     : 0.f;
            v.y = (t0 + u + 1 < TN) ? src[u + 1] : 0.f;
            v.z = (t0 + u + 2 < TN) ? src[u + 2] : 0.f;
            v.w = 0.f;
        }
        *reinterpret_cast<float4*>(&Xs[c * 132 + u]) = v;
    }
    for (int idx = tid; idx < 128 * 64; idx += 256) Rs[idx] = rw[idx];
    __syncthreads();

    int tg = tid >> 3, fg = tid & 7;
    int f0 = fg * 8, u0 = tg * 4;

    ull acc[4][4];
    #pragma unroll
    for (int jj = 0; jj < 4; jj++) {
        ull bj = pk2(rb[f0 + 2 * jj], rb[f0 + 2 * jj + 1]);
        #pragma unroll
        for (int i = 0; i < 4; i++) acc[i][jj] = bj;
    }

    #pragma unroll 4
    for (int c = 0; c < 128; c++) {
        ull xd[4];
        #pragma unroll
        for (int s = 0; s < 4; s++) xd[s] = d2(Xs[c * 132 + u0 + s]);
        const ull* rp = reinterpret_cast<const ull*>(&Rs[c * 64 + f0]);
        #pragma unroll
        for (int jj = 0; jj < 4; jj++) {
            ull wv = rp[jj];
            #pragma unroll
            for (int i = 0; i < 4; i++) fma2(acc[i][jj], xd[i], wv);
        }
    }

    #pragma unroll
    for (int i = 0; i < 4; i++) {
        int t = t0 + u0 + i;
        if (t < TN) {
            float v8[8];
            #pragma unroll
            for (int jj = 0; jj < 4; jj++) up2(acc[i][jj], v8[2 * jj], v8[2 * jj + 1]);
            float* op = g_res + ((size_t)b * TN + t) * 64 + f0;
            *reinterpret_cast<float4*>(op) = make_float4(v8[0], v8[1], v8[2], v8[3]);
            *reinterpret_cast<float4*>(op + 4) = make_float4(v8[4], v8[5], v8[6], v8[7]);
        }
    }
}

// ---------------- conv1 (C=128 -> F=64) + LN + relu + (precomputed res) ------
__global__ void __launch_bounds__(512, 1)
k_conv1(const float* __restrict__ X,
        const float* __restrict__ w1, const float* __restrict__ b1,
        const float* __restrict__ lns, const float* __restrict__ lnb) {
    extern __shared__ float sm[];
    float* Xs = sm;                 // 128 x 258
    float* Ws = sm + 128 * 258;     // 3*128*64
    int b = blockIdx.y;
    int t0 = blockIdx.x * 256;
    int tid = threadIdx.x;
    int warp = tid >> 5, lane = tid & 31;
    const float* Xb = X + (size_t)b * CC * TN;

    for (int c = warp; c < 128; c += 16) {
        const float* src = Xb + (size_t)c * TN;
        for (int u = lane; u < 258; u += 32) {
            int t = t0 - 1 + u;
            Xs[c * 258 + u] = (t >= 0 && t < TN) ? src[t] : 0.f;
        }
    }
    for (int idx = tid; idx < 3 * 128 * 64; idx += 512) Ws[idx] = w1[idx];
    __syncthreads();

    int tg = tid >> 3, fg = tid & 7;
    int f0 = fg * 8, u0 = tg * 4;

    float ls[8], lb[8];
    ull acc[4][4];
    #pragma unroll
    for (int jj = 0; jj < 4; jj++) {
        ull bj = pk2(b1[f0 + 2 * jj], b1[f0 + 2 * jj + 1]);
        #pragma unroll
        for (int i = 0; i < 4; i++) acc[i][jj] = bj;
    }
    #pragma unroll
    for (int j = 0; j < 8; j++) { ls[j] = lns[f0 + j]; lb[j] = lnb[f0 + j]; }

    for (int c = 0; c < 128; c++) {
        ull xd[6];
        #pragma unroll
        for (int s = 0; s < 6; s++) xd[s] = d2(Xs[c * 258 + u0 + s]);
        #pragma unroll
        for (int tap = 0; tap < 3; tap++) {
            const ull* wp = reinterpret_cast<const ull*>(&Ws[tap * 8192 + c * 64 + f0]);
            #pragma unroll
            for (int jj = 0; jj < 4; jj++) {
                ull wv = wp[jj];
                #pragma unroll
                for (int i = 0; i < 4; i++) fma2(acc[i][jj], xd[i + tap], wv);
            }
        }
    }

    #pragma unroll
    for (int i = 0; i < 4; i++) {
        float a8[8];
        #pragma unroll
        for (int jj = 0; jj < 4; jj++) up2(acc[i][jj], a8[2 * jj], a8[2 * jj + 1]);
        float s = 0.f, ss = 0.f;
        #pragma unroll
        for (int j = 0; j < 8; j++) { s += a8[j]; ss += a8[j] * a8[j]; }
        #pragma unroll
        for (int o = 1; o < 8; o <<= 1) {
            s  += __shfl_xor_sync(0xffffffffu, s, o);
            ss += __shfl_xor_sync(0xffffffffu, ss, o);
        }
        float m = s * (1.0f / 64.0f);
        float v = ss * (1.0f / 64.0f) - m * m;
        float rstd = rsqrtf(v + 1e-6f);
        int t = t0 + u0 + i;
        if (t < TN) {
            const float* rp = g_res + ((size_t)b * TN + t) * 64 + f0;
            float4 r0v = *reinterpret_cast<const float4*>(rp);
            float4 r1v = *reinterpret_cast<const float4*>(rp + 4);
            float r8[8] = {r0v.x, r0v.y, r0v.z, r0v.w, r1v.x, r1v.y, r1v.z, r1v.w};
            float o8[8];
            #pragma unroll
            for (int j = 0; j < 8; j++) {
                float h = fmaxf((a8[j] - m) * rstd * ls[j] + lb[j], 0.f);
                o8[j] = h + r8[j];
            }
            float* op = g_t1 + ((size_t)b * TN + t) * 64 + f0;
            *reinterpret_cast<float4*>(op) = make_float4(o8[0], o8[1], o8[2], o8[3]);
            *reinterpret_cast<float4*>(op + 4) = make_float4(o8[4], o8[5], o8[6], o8[7]);
        }
    }
}

// ---------------- conv (F->F, dilation D) + LN + relu + identity res ---------
template <int D>
__global__ void __launch_bounds__(256, 2)
k_convres(const float* __restrict__ in,
          const float* __restrict__ w, const float* __restrict__ bias,
          const float* __restrict__ lns, const float* __restrict__ lnb,
          float* __restrict__ outp) {
    extern __shared__ float sm[];
    const int ROWS = 128 + 2 * D;
    float* Ts = sm;                 // ROWS x 65
    float* Ws = sm + ROWS * 65;     // 3*64*64
    int b = blockIdx.y;
    int t0 = blockIdx.x * 128;
    int tid = threadIdx.x;
    const float* inb = in + (size_t)b * TN * 64;

    for (int idx = tid; idx < ROWS * 64; idx += 256) {
        int u = idx >> 6, f = idx & 63;
        int t = t0 - D + u;
        Ts[u * 65 + f] = (t >= 0 && t < TN) ? inb[(size_t)t * 64 + f] : 0.f;
    }
    for (int idx = tid; idx < 3 * 64 * 64; idx += 256) Ws[idx] = w[idx];
    __syncthreads();

    int tg = tid >> 3, fg = tid & 7;
    int f0 = fg * 8;
    int u0 = tg * 4;

    float ls[8], lb[8];
    ull acc[4][4];
    #pragma unroll
    for (int jj = 0; jj < 4; jj++) {
        ull bj = pk2(bias[f0 + 2 * jj], bias[f0 + 2 * jj + 1]);
        #pragma unroll
        for (int i = 0; i < 4; i++) acc[i][jj] = bj;
    }
    #pragma unroll
    for (int j = 0; j < 8; j++) { ls[j] = lns[f0 + j]; lb[j] = lnb[f0 + j]; }

    for (int c = 0; c < 64; c++) {
        ull xd[2 * D + 4];
        #pragma unroll
        for (int s = 0; s < 2 * D + 4; s++) xd[s] = d2(Ts[(u0 + s) * 65 + c]);
        #pragma unroll
        for (int tap = 0; tap < 3; tap++) {
            const ull* wp = reinterpret_cast<const ull*>(&Ws[tap * 4096 + c * 64 + f0]);
            #pragma unroll
            for (int jj = 0; jj < 4; jj++) {
                ull wv = wp[jj];
                #pragma unroll
                for (int i = 0; i < 4; i++) fma2(acc[i][jj], xd[i + tap * D], wv);
            }
        }
    }

    #pragma unroll
    for (int i = 0; i < 4; i++) {
        float a8[8];
        #pragma unroll
        for (int jj = 0; jj < 4; jj++) up2(acc[i][jj], a8[2 * jj], a8[2 * jj + 1]);
        float s = 0.f, ss = 0.f;
        #pragma unroll
        for (int j = 0; j < 8; j++) { s += a8[j]; ss += a8[j] * a8[j]; }
        #pragma unroll
        for (int o = 1; o < 8; o <<= 1) {
            s  += __shfl_xor_sync(0xffffffffu, s, o);
            ss += __shfl_xor_sync(0xffffffffu, ss, o);
        }
        float m = s * (1.0f / 64.0f);
        float v = ss * (1.0f / 64.0f) - m * m;
        float rstd = rsqrtf(v + 1e-6f);
        int t = t0 + u0 + i;
        if (t < TN) {
            float o8[8];
            #pragma unroll
            for (int j = 0; j < 8; j++) {
                float h = fmaxf((a8[j] - m) * rstd * ls[j] + lb[j], 0.f);
                o8[j] = h + Ts[(u0 + i + D) * 65 + f0 + j];
            }
            float* op = outp + ((size_t)b * TN + t) * 64 + f0;
            *reinterpret_cast<float4*>(op) = make_float4(o8[0], o8[1], o8[2], o8[3]);
            *reinterpret_cast<float4*>(op + 4) = make_float4(o8[4], o8[5], o8[6], o8[7]);
        }
    }
}

// ---------------- node_feats = X @ tcn_out, K split over 2 CTAs --------------
__global__ void k_nf(const float* __restrict__ X) {
    __shared__ float Xs[128][33];
    __shared__ float Ts[32][64];
    int half = blockIdx.x;
    int b = blockIdx.y;
    int tid = threadIdx.x;
    int c0 = (tid >> 4) * 8;
    int f0 = (tid & 15) * 4;
    ull acc[8][2];
    #pragma unroll
    for (int r = 0; r < 8; r++) { acc[r][0] = 0ull; acc[r][1] = 0ull; }

    const float* Xb = X + (size_t)b * CC * TN;
    const float* Tb = g_tcn + (size_t)b * TN * 64;
    int kbeg = half * 1000, kend = kbeg + 1000;

    for (int k0 = kbeg; k0 < kend; k0 += 32) {
        for (int idx = tid; idx < 128 * 32; idx += 256) {
            int c = idx >> 5, kk = idx & 31;
            int k = k0 + kk;
            Xs[c][kk] = (k < kend) ? Xb[(size_t)c * TN + k] : 0.f;
        }
        for (int idx = tid; idx < 32 * 64; idx += 256) {
            int kk = idx >> 6, f = idx & 63;
            int k = k0 + kk;
            Ts[kk][f] = (k < kend) ? Tb[(size_t)k * 64 + f] : 0.f;
        }
        __syncthreads();
        #pragma unroll 4
        for (int kk = 0; kk < 32; kk++) {
            const ull* tp = reinterpret_cast<const ull*>(&Ts[kk][f0]);
            ull t0v = tp[0], t1v = tp[1];
            #pragma unroll
            for (int r = 0; r < 8; r++) {
                ull xd = d2(Xs[c0 + r][kk]);
                fma2(acc[r][0], xd, t0v);
                fma2(acc[r][1], xd, t1v);
            }
        }
        __syncthreads();
    }
    #pragma unroll
    for (int r = 0; r < 8; r++) {
        float v4[4];
        up2(acc[r][0], v4[0], v4[1]);
        up2(acc[r][1], v4[2], v4[3]);
        float* o = g_nf + (size_t)half * BB * CC * FF + ((size_t)b * 128 + c0 + r) * 64 + f0;
        *reinterpret_cast<float4*>(o) = make_float4(v4[0], v4[1], v4[2], v4[3]);
    }
}

// ---------------- geo = relu(LN(adj @ node_feats)) ---------------------------
__global__ void k_geo(const float* __restrict__ lns, const float* __restrict__ lnb) {
    extern __shared__ float sm[];
    float* adjs = sm;                // 128 x 129 (pad)
    float* nfs = sm + 128 * 129;     // 128 x 64
    int b = blockIdx.x, tid = threadIdx.x;   // 128 threads
    for (int idx = tid; idx < 128 * 64; idx += 128)
        nfs[idx] = g_nf[(size_t)b * 8192 + idx] + g_nf[(size_t)BB * 8192 + (size_t)b * 8192 + idx];
    {
        const float* src = g_adj + (size_t)b * 16384;
        for (int idx = tid; idx < 16384; idx += 128) {
            int i = idx >> 7, j = idx & 127;
            adjs[i * 129 + j] = src[idx];
        }
    }
    __syncthreads();

    const float* arow = adjs + tid * 129;
    ull acc[32];
    #pragma unroll
    for (int q = 0; q < 32; q++) acc[q] = 0ull;
    #pragma unroll 2
    for (int j = 0; j < 128; j++) {
        ull a = d2(arow[j]);
        const ull* n2 = reinterpret_cast<const ull*>(&nfs[j * 64]);
        #pragma unroll
        for (int q = 0; q < 32; q++) fma2(acc[q], a, n2[q]);
    }
    float av[64];
    #pragma unroll
    for (int q = 0; q < 32; q++) up2(acc[q], av[2 * q], av[2 * q + 1]);
    float s = 0.f, ss = 0.f;
    #pragma unroll
    for (int j = 0; j < 64; j++) { s += av[j]; ss += av[j] * av[j]; }
    float m = s * (1.0f / 64.0f);
    float v = ss * (1.0f / 64.0f) - m * m;
    float rstd = rsqrtf(v + 1e-6f);
    float* o = g_geo + ((size_t)b * 128 + tid) * 64;
    #pragma unroll
    for (int j = 0; j < 64; j++)
        o[j] = fmaxf((av[j] - m) * rstd * lns[j] + lnb[j], 0.f);
}

// ---------------- decay GEMV partials: 4 K-chunks per batch row --------------
__global__ void k_decay(const float* __restrict__ dw) {
    __shared__ float gs[2048];
    int part = blockIdx.x, b = blockIdx.y;
    int tid = threadIdx.x;  // 128 threads
    int kbeg = part * 2048;
    for (int idx = tid; idx < 2048; idx += 128)
        gs[idx] = g_geo[(size_t)b * 8192 + kbeg + idx];
    __syncthreads();
    float a0 = 0.f, a1 = 0.f, a2 = 0.f, a3 = 0.f;
    for (int k = 0; k < 2048; k += 4) {
        a0 += gs[k + 0] * dw[(size_t)(kbeg + k + 0) * 128 + tid];
        a1 += gs[k + 1] * dw[(size_t)(kbeg + k + 1) * 128 + tid];
        a2 += gs[k + 2] * dw[(size_t)(kbeg + k + 2) * 128 + tid];
        a3 += gs[k + 3] * dw[(size_t)(kbeg + k + 3) * 128 + tid];
    }
    g_dpart[((size_t)part * BB + b) * HH + tid] = (a0 + a1) + (a2 + a3);
}

// ---------------- chunk-mean pool of tcn + seq_w GEMM ------------------------
__global__ void k_poolseq(const float* __restrict__ sw, const float* __restrict__ sb) {
    __shared__ float ps[64];
    int s = blockIdx.x, b = blockIdx.y, tid = threadIdx.x;  // 128 threads
    if (tid < 64) {
        const float* base = g_tcn + ((size_t)b * TN + s * 200) * 64 + tid;
        float a = 0.f;
        #pragma unroll 8
        for (int t = 0; t < 200; t++) a += base[(size_t)t * 64];
        ps[tid] = a * (1.0f / 200.0f);
    }
    __syncthreads();
    float acc = sb[tid];
    #pragma unroll
    for (int f = 0; f < 64; f++) acc += ps[f] * sw[f * 128 + tid];
    g_seqin[((size_t)b * SEQN + s) * 128 + tid] = acc;
}

// ---------------- LIF scan + attention + heads -------------------------------
__global__ void k_lif(const float* __restrict__ db,
                      const float* __restrict__ aw, const float* __restrict__ ab,
                      const float* __restrict__ fw, const float* __restrict__ fb,
                      const float* __restrict__ ow, const float* __restrict__ ob,
                      float* __restrict__ dout) {
    __shared__ float red[128];
    __shared__ float attn[SEQN];
    __shared__ float featv[128];
    __shared__ float f2[64];
    int b = blockIdx.x, h = threadIdx.x;   // 128 threads

    float dacc = db[h]
        + g_dpart[((size_t)0 * BB + b) * HH + h]
        + g_dpart[((size_t)1 * BB + b) * HH + h]
        + g_dpart[((size_t)2 * BB + b) * HH + h]
        + g_dpart[((size_t)3 * BB + b) * HH + h];
    float d = 1.0f / (1.0f + expf(-dacc));

    float mem = 0.f, spsum = 0.f;
    float sp[SEQN];
    #pragma unroll
    for (int s = 0; s < SEQN; s++) {
        mem = mem * d + g_seqin[((size_t)b * SEQN + s) * 128 + h];
        float spike = (mem - 0.5f) > 0.f ? 1.0f : 0.0f;
        sp[s] = spike;
        spsum += spike;
        mem -= 0.5f * spike;
    }
    float awh = aw[h];
    for (int s = 0; s < SEQN; s++) {
        red[h] = sp[s] * awh;
        __syncthreads();
        for (int o = 64; o; o >>= 1) {
            if (h < o) red[h] += red[h + o];
            __syncthreads();
        }
        if (h == 0) attn[s] = red[0] + ab[0];
        __syncthreads();
    }
    red[h] = spsum;
    __syncthreads();
    for (int o = 64; o; o >>= 1) {
        if (h < o) red[h] += red[h + o];
        __syncthreads();
    }
    if (h == 0) atomicAdd(&g_spksum, red[0]);

    if (h == 0) {
        float mx = -1e30f;
        for (int s = 0; s < SEQN; s++) mx = fmaxf(mx, attn[s]);
        float ssum = 0.f;
        for (int s = 0; s < SEQN; s++) { attn[s] = expf(attn[s] - mx); ssum += attn[s]; }
        float inv = 1.0f / ssum;
        for (int s = 0; s < SEQN; s++) attn[s] *= inv;
    }
    __syncthreads();

    float fv = 0.f;
    #pragma unroll
    for (int s = 0; s < SEQN; s++) fv += sp[s] * attn[s];
    featv[h] = fv;
    __syncthreads();

    if (h < 64) {
        float acc = fb[h];
        for (int k = 0; k < 128; k++) acc += featv[k] * fw[k * 64 + h];
        f2[h] = fmaxf(acc, 0.f);
    }
    __syncthreads();
    if (h < 4) {
        float acc = ob[h];
        for (int j = 0; j < 64; j++) acc += f2[j] * ow[j * 4 + h];
        dout[b * 4 + h] = acc;
    }
}

__global__ void k_finmean(float* __restrict__ dout, int osz) {
    if (threadIdx.x == 0)
        dout[osz - 1] = g_spksum * (1.0f / ((float)BB * SEQN * HH));
}

// ---------------- launcher ----------------------------------------------------
extern "C" void kernel_launch(void* const* d_in, const int* in_sizes, int n_in,
                              void* d_out, int out_size) {
    const float* X    = (const float*)d_in[0];
    const float* c1w  = (const float*)d_in[1];
    const float* c1b  = (const float*)d_in[2];
    const float* l1s  = (const float*)d_in[3];
    const float* l1b  = (const float*)d_in[4];
    const float* r1w  = (const float*)d_in[5];
    const float* r1b  = (const float*)d_in[6];
    const float* c2w  = (const float*)d_in[7];
    const float* c2b  = (const float*)d_in[8];
    const float* l2s  = (const float*)d_in[9];
    const float* l2b  = (const float*)d_in[10];
    const float* c3w  = (const float*)d_in[11];
    const float* c3b  = (const float*)d_in[12];
    const float* l3s  = (const float*)d_in[13];
    const float* l3b  = (const float*)d_in[14];
    const float* lgs  = (const float*)d_in[15];
    const float* lgb  = (const float*)d_in[16];
    const float* seqw = (const float*)d_in[19];
    const float* seqb = (const float*)d_in[20];
    const float* dw   = (const float*)d_in[21];
    const float* db   = (const float*)d_in[22];
    const float* aw   = (const float*)d_in[23];
    const float* ab   = (const float*)d_in[24];
    const float* fw   = (const float*)d_in[25];
    const float* fb   = (const float*)d_in[26];
    const float* ow   = (const float*)d_in[27];
    const float* ob   = (const float*)d_in[28];
    float* out = (float*)d_out;

    float *t1p, *t2p, *tcnp;
    cudaGetSymbolAddress((void**)&t1p, g_t1);
    cudaGetSymbolAddress((void**)&t2p, g_t2);
    cudaGetSymbolAddress((void**)&tcnp, g_tcn);

    size_t sm_log = (size_t)2 * 128 * 128 * sizeof(float);                 // 128 KB
    size_t sm_c1  = (size_t)(128 * 258 + 3 * 128 * 64) * sizeof(float);    // 225 KB
    size_t sm_res = (size_t)(128 * 132 + 128 * 64) * sizeof(float);        // ~98 KB
    size_t sm_c2  = (size_t)(132 * 65 + 3 * 64 * 64) * sizeof(float);
    size_t sm_c3  = (size_t)(136 * 65 + 3 * 64 * 64) * sizeof(float);
    size_t sm_geo = (size_t)(128 * 129 + 128 * 64) * sizeof(float);        // ~98 KB
    cudaFuncSetAttribute(k_logadj, cudaFuncAttributeMaxDynamicSharedMemorySize, (int)sm_log);
    cudaFuncSetAttribute(k_conv1, cudaFuncAttributeMaxDynamicSharedMemorySize, (int)sm_c1);
    cudaFuncSetAttribute(k_res, cudaFuncAttributeMaxDynamicSharedMemorySize, (int)sm_res);
    cudaFuncSetAttribute(k_convres<2>, cudaFuncAttributeMaxDynamicSharedMemorySize, (int)sm_c2);
    cudaFuncSetAttribute(k_convres<4>, cudaFuncAttributeMaxDynamicSharedMemorySize, (int)sm_c3);
    cudaFuncSetAttribute(k_geo, cudaFuncAttributeMaxDynamicSharedMemorySize, (int)sm_geo);

    cudaStream_t s2 = 0;
    cudaEvent_t e1 = 0, e2 = 0;
    bool fork = true;
    if (cudaStreamCreateWithFlags(&s2, cudaStreamNonBlocking) != cudaSuccess) fork = false;
    if (fork && cudaEventCreateWithFlags(&e1, cudaEventDisableTiming) != cudaSuccess) fork = false;
    if (fork && cudaEventCreateWithFlags(&e2, cudaEventDisableTiming) != cudaSuccess) fork = false;

    k_mean<<<(BB * CC * 32) / 256, 256>>>(X);

    if (fork) {
        cudaEventRecord(e1, 0);
        cudaStreamWaitEvent(s2, e1, 0);
        k_cov<<<BB, 256, 0, s2>>>(X);
        k_logadj<<<BB, 256, sm_log, s2>>>();
        cudaEventRecord(e2, s2);
    } else {
        k_cov<<<BB, 256>>>(X);
        k_logadj<<<BB, 256, sm_log>>>();
    }

    {
        dim3 gr(16, BB);
        k_res<<<gr, 256, sm_res>>>(X, r1w, r1b);
        dim3 g1(8, BB);
        k_conv1<<<g1, 512, sm_c1>>>(X, c1w, c1b, l1s, l1b);
        dim3 g(16, BB);
        k_convres<2><<<g, 256, sm_c2>>>(t1p, c2w, c2b, l2s, l2b, t2p);
        k_convres<4><<<g, 256, sm_c3>>>(t2p, c3w, c3b, l3s, l3b, tcnp);
    }
    {
        dim3 g(2, BB);
        k_nf<<<g, 256>>>(X);
    }
    {
        dim3 g(SEQN, BB);
        k_poolseq<<<g, 128>>>(seqw, seqb);
    }

    if (fork) cudaStreamWaitEvent(0, e2, 0);

    k_geo<<<BB, 128, sm_geo>>>(lgs, lgb);
    {
        dim3 g(4, BB);
        k_decay<<<g, 128>>>(dw);
    }
    k_lif<<<BB, 128>>>(db, aw, ab, fw, fb, ow, ob, out);
    k_finmean<<<1, 32>>>(out, out_size);
}